// round 8
// baseline (speedup 1.0000x reference)
#include <cuda_runtime.h>
#include <cstdint>

#define NGRAPH 4096
#define EPS 1e-6f

// ---------------- device scratch ----------------
__device__ __align__(16) float g_att[262144 * 8];          // exp attention, unnormalized [N,8]
__device__ __align__(16) float g_outflat[NGRAPH * 1024];   // aggregated [B, H*D]
__device__ __align__(16) float g_W3h[1024 * 128];
__device__ __align__(16) float g_W3l[1024 * 128];
__device__ __align__(16) float g_W4h[128 * 128];
__device__ __align__(16) float g_W4l[128 * 128];
__device__ int g_is64;

__device__ __forceinline__ float leaky(float x){ return x > 0.f ? x : 0.01f * x; }

__device__ __forceinline__ float tf32_rn(float x){
    uint32_t u;
    asm("cvt.rna.tf32.f32 %0, %1;" : "=r"(u) : "f"(x));
    return __uint_as_float(u);
}

__device__ __forceinline__ void mma_tf32(float* c,
    float a0, float a1, float a2, float a3, float b0, float b1){
    asm volatile(
      "mma.sync.aligned.m16n8k8.row.col.f32.tf32.tf32.f32 "
      "{%0,%1,%2,%3}, {%4,%5,%6,%7}, {%8,%9}, {%0,%1,%2,%3};\n"
      : "+f"(c[0]), "+f"(c[1]), "+f"(c[2]), "+f"(c[3])
      : "r"(__float_as_uint(a0)), "r"(__float_as_uint(a1)),
        "r"(__float_as_uint(a2)), "r"(__float_as_uint(a3)),
        "r"(__float_as_uint(b0)), "r"(__float_as_uint(b1)));
}

// packed f32x2 ops (B300 FFMA2 path)
#define FMA2(d, a, b, c) asm("fma.rn.f32x2 %0, %1, %2, %3;" : "=l"(d) : "l"(a), "l"(b), "l"(c))
#define ADD2(d, a, b)    asm("add.rn.f32x2 %0, %1, %2;"     : "=l"(d) : "l"(a), "l"(b))
#define PACK2(d, lo, hi) asm("mov.b64 %0, {%1, %2};"        : "=l"(d) : "r"(__float_as_uint(lo)), "r"(__float_as_uint(hi)))

__global__ void detect_kernel(const int* __restrict__ batch, int n){
    __shared__ int bad;
    if (threadIdx.x == 0) bad = 0;
    __syncthreads();
    int base = n / 2;
    int i = threadIdx.x;
    int lo = batch[base + 2*i];
    int hi = batch[base + 2*i + 1];
    if (hi != 0 || lo < 0 || lo >= NGRAPH) bad = 1;
    __syncthreads();
    if (threadIdx.x == 0) g_is64 = (bad == 0);
}

__device__ __forceinline__ int bat(const int* b, int i, int is64){
    return is64 ? b[2*i] : b[i];
}

__device__ __forceinline__ int lbound(const int* b, int n, int val, int is64){
    int lo = 0, hi = n;
    while (lo < hi){
        int mid = (lo + hi) >> 1;
        if (bat(b, mid, is64) < val) lo = mid + 1; else hi = mid;
    }
    return lo;
}

// ---------------- weight prep: one-time tf32 hi/lo split of W3, W4 ----------------
__global__ void prep_kernel(const float* __restrict__ W3, const float* __restrict__ W4){
    int i = blockIdx.x * 256 + threadIdx.x;
    if (i < 1024*128){
        float w = W3[i];
        float h = tf32_rn(w);
        g_W3h[i] = h; g_W3l[i] = tf32_rn(w - h);
    }
    int j = i - 1024*128;
    if (j >= 0 && j < 128*128){
        float w = W4[j];
        float h = tf32_rn(w);
        g_W4h[j] = h; g_W4l[j] = tf32_rn(w - h);
    }
}

// ---------------- Pass A: fused GEMM1(tf32 mma) + leaky + LN + GEMM2 + exp ----------------
// 64 rows / block, 256 threads (8 warps: 4 m-tiles x 2 n-halves), 4096 blocks.
// W1 converted hi/lo ONCE at staging. Strides: sA 132 (bank 4g+t4), sW1 72 (bank 8t4+g).
#define AS 132
#define WS 72
#define ATT_SMEM_FLOATS (8448 + 9216 + 9216 + 512 + 64*3 + 8 + 128)

__global__ __launch_bounds__(256) void att_kernel(
    const float* __restrict__ feat,
    const float* __restrict__ W1, const float* __restrict__ b1,
    const float* __restrict__ g1, const float* __restrict__ be1,
    const float* __restrict__ W2, const float* __restrict__ b2)
{
    extern __shared__ float sm[];
    float* sA   = sm;               // 64 x 132 = 8448 (aliased later as sH stride 65)
    float* sW1h = sA + 8448;        // 128 x 72 = 9216
    float* sW1l = sW1h + 9216;      // 9216
    float* sW2  = sW1l + 9216;      // 512
    float* sB1  = sW2 + 512;        // 64
    float* sG1  = sB1 + 64;         // 64
    float* sBe1 = sG1 + 64;         // 64
    float* sB2  = sBe1 + 64;        // 8
    float* sMu  = sB2 + 8;          // 64
    float* sIs  = sMu + 64;         // 64
    float* sH   = sA;               // alias, stride 65 (4160 <= 8448)

    int t = threadIdx.x;
    int row0 = blockIdx.x * 64;
    int wid = t >> 5, lane = t & 31;
    int g = lane >> 2, t4 = lane & 3;
    int mw = wid & 3, nw = wid >> 2;

    {   // stage feat 64x128 (2048 float4, 8/thread)
        const float4* gsrc = (const float4*)(feat + (size_t)row0 * 128);
        #pragma unroll
        for (int e = 0; e < 8; e++){
            int i4 = t + 256*e;
            int r = i4 >> 5, c4 = i4 & 31;
            *(float4*)&sA[r*AS + 4*c4] = gsrc[i4];
        }
    }
    {   // stage W1 128x64 as hi/lo (2048 float4, 8/thread)
        const float4* gsrc = (const float4*)W1;
        #pragma unroll
        for (int e = 0; e < 8; e++){
            int i4 = t + 256*e;
            int k = i4 >> 4, c4 = i4 & 15;
            float4 w = gsrc[i4];
            float4 h, l;
            h.x = tf32_rn(w.x); l.x = tf32_rn(w.x - h.x);
            h.y = tf32_rn(w.y); l.y = tf32_rn(w.y - h.y);
            h.z = tf32_rn(w.z); l.z = tf32_rn(w.z - h.z);
            h.w = tf32_rn(w.w); l.w = tf32_rn(w.w - h.w);
            *(float4*)&sW1h[k*WS + 4*c4] = h;
            *(float4*)&sW1l[k*WS + 4*c4] = l;
        }
    }
    if (t < 128) ((float4*)sW2)[t] = ((const float4*)W2)[t];
    if (t < 64){ sB1[t] = b1[t]; sG1[t] = g1[t]; sBe1[t] = be1[t]; }
    if (t < 8)  sB2[t] = b2[t];
    __syncthreads();

    // GEMM1: warp = rows [mw*16, +16), cols [nw*32, +32)
    int rbase = mw * 16, cbase = nw * 32;
    float acc[4][4];
    #pragma unroll
    for (int j = 0; j < 4; j++){ acc[j][0]=acc[j][1]=acc[j][2]=acc[j][3]=0.f; }

    const float* A0 = sA + (rbase + g) * AS;
    const float* A1 = A0 + 8 * AS;

    #pragma unroll 4
    for (int ks = 0; ks < 16; ks++){
        int k0 = ks * 8;
        float a0 = A0[k0+t4],   a1 = A1[k0+t4];
        float a2 = A0[k0+t4+4], a3 = A1[k0+t4+4];
        float ah0=tf32_rn(a0), ah1=tf32_rn(a1), ah2=tf32_rn(a2), ah3=tf32_rn(a3);
        float al0=tf32_rn(a0-ah0), al1=tf32_rn(a1-ah1), al2=tf32_rn(a2-ah2), al3=tf32_rn(a3-ah3);
        const float* Bh = sW1h + (k0 + t4) * WS + cbase + g;
        const float* Bl = sW1l + (k0 + t4) * WS + cbase + g;
        #pragma unroll
        for (int j = 0; j < 4; j++){
            float bh0 = Bh[j*8], bh1 = Bh[4*WS + j*8];
            float bl0 = Bl[j*8], bl1 = Bl[4*WS + j*8];
            mma_tf32(acc[j], ah0,ah1,ah2,ah3, bh0,bh1);
            mma_tf32(acc[j], al0,al1,al2,al3, bh0,bh1);
            mma_tf32(acc[j], ah0,ah1,ah2,ah3, bl0,bl1);
        }
    }
    __syncthreads();   // all sA reads complete before aliasing as sH

    {   // epilogue: bias + leaky -> sH (stride 65)
        int rA = rbase + g, rB = rA + 8;
        #pragma unroll
        for (int j = 0; j < 4; j++){
            int c = cbase + j*8 + 2*t4;
            sH[rA*65 + c]     = leaky(acc[j][0] + sB1[c]);
            sH[rA*65 + c + 1] = leaky(acc[j][1] + sB1[c+1]);
            sH[rB*65 + c]     = leaky(acc[j][2] + sB1[c]);
            sH[rB*65 + c + 1] = leaky(acc[j][3] + sB1[c+1]);
        }
    }
    __syncthreads();

    if (t < 64){   // LN stats per row
        float sum = 0.f, ss = 0.f;
        #pragma unroll 8
        for (int j = 0; j < 64; j++){ float v = sH[t*65 + j]; sum += v; ss += v*v; }
        float mu = sum * (1.f/64.f);
        float var = ss * (1.f/64.f) - mu*mu;
        sMu[t] = mu; sIs[t] = rsqrtf(var + EPS);
    }
    __syncthreads();

    if (t < 128){   // GEMM2 (64->8) + exp, 2 threads per row x 4 outputs
        int row = t >> 1, half = t & 1, kb = half * 4;
        float mu = sMu[row], is = sIs[row];
        float a0=0.f, a1=0.f, a2=0.f, a3=0.f;
        #pragma unroll 4
        for (int j = 0; j < 64; j++){
            float hn = (sH[row*65 + j] - mu) * is * sG1[j] + sBe1[j];
            a0 += hn * sW2[j*8 + kb + 0];
            a1 += hn * sW2[j*8 + kb + 1];
            a2 += hn * sW2[j*8 + kb + 2];
            a3 += hn * sW2[j*8 + kb + 3];
        }
        int grow = row0 + row;
        float4 o;
        o.x = __expf(a0 + sB2[kb+0]);
        o.y = __expf(a1 + sB2[kb+1]);
        o.z = __expf(a2 + sB2[kb+2]);
        o.w = __expf(a3 + sB2[kb+3]);
        *(float4*)&g_att[grow*8 + kb] = o;
    }
}

// ---------------- Pass B: block-per-graph, 8 row-parallel warps, f32x2 math ----------------
// Each warp handles rows lo+w, lo+w+8, ...; lane owns feat cols [4*lane, 4*lane+4).
// acc[c][p] packs heads (2p, 2p+1). End-of-block smem reduction.
__global__ __launch_bounds__(256) void aggregate_kernel(
    const float* __restrict__ feat, const int* __restrict__ batchp, int nrows)
{
    int gi = blockIdx.x;
    __shared__ int s_lo, s_hi;
    __shared__ __align__(16) float sS[8][8];
    __shared__ float sInvF[8];
    __shared__ __align__(16) unsigned long long sRedU[8][512];

    int is64 = g_is64;
    int t = threadIdx.x;
    int w = t >> 5, lane = t & 31;
    if (t == 0)  s_lo = lbound(batchp, nrows, gi, is64);
    if (t == 32) s_hi = lbound(batchp, nrows, gi + 1, is64);
    __syncthreads();
    int lo = s_lo, hi = s_hi;

    unsigned long long acc[4][4];   // [feat col c][head pair p]
    #pragma unroll
    for (int c = 0; c < 4; c++)
        #pragma unroll
        for (int p = 0; p < 4; p++) acc[c][p] = 0ull;
    unsigned long long s[4] = {0ull, 0ull, 0ull, 0ull};

    const float4* feat4 = (const float4*)feat;
    for (int r = lo + w; r < hi; r += 8){
        float4 f = feat4[(size_t)r * 32 + lane];
        ulonglong2 A01 = *(const ulonglong2*)&g_att[(size_t)r * 8];      // (h0,h1),(h2,h3)
        ulonglong2 A45 = *(const ulonglong2*)&g_att[(size_t)r * 8 + 4];  // (h4,h5),(h6,h7)
        unsigned long long f2[4];
        PACK2(f2[0], f.x, f.x); PACK2(f2[1], f.y, f.y);
        PACK2(f2[2], f.z, f.z); PACK2(f2[3], f.w, f.w);
        ADD2(s[0], s[0], A01.x); ADD2(s[1], s[1], A01.y);
        ADD2(s[2], s[2], A45.x); ADD2(s[3], s[3], A45.y);
        #pragma unroll
        for (int c = 0; c < 4; c++){
            FMA2(acc[c][0], f2[c], A01.x, acc[c][0]);
            FMA2(acc[c][1], f2[c], A01.y, acc[c][1]);
            FMA2(acc[c][2], f2[c], A45.x, acc[c][2]);
            FMA2(acc[c][3], f2[c], A45.y, acc[c][3]);
        }
    }

    #pragma unroll
    for (int p = 0; p < 4; p++)
        #pragma unroll
        for (int c = 0; c < 4; c++)
            sRedU[w][p*128 + lane*4 + c] = acc[c][p];
    if (lane < 4) *(unsigned long long*)&sS[w][2*lane] = s[lane];
    __syncthreads();

    if (t < 8){
        float tot = 0.f;
        #pragma unroll
        for (int w2 = 0; w2 < 8; w2++) tot += sS[w2][t];
        sInvF[t] = (hi > lo) ? 1.f / tot : 0.f;
    }
    __syncthreads();

    #pragma unroll
    for (int e = 0; e < 2; e++){
        int slot = t + 256*e;
        unsigned long long tot = 0ull;
        #pragma unroll
        for (int w2 = 0; w2 < 8; w2++) ADD2(tot, tot, sRedU[w2][slot]);
        int p = slot >> 7, col = slot & 127;
        uint32_t lo32 = (uint32_t)tot, hi32 = (uint32_t)(tot >> 32);
        float vlo = __uint_as_float(lo32) * sInvF[2*p];
        float vhi = __uint_as_float(hi32) * sInvF[2*p + 1];
        g_outflat[(size_t)gi*1024 + (2*p)*128 + col]     = vlo;
        g_outflat[(size_t)gi*1024 + (2*p + 1)*128 + col] = vhi;
    }
}

// ---------------- Pass C: GEMM3(tf32)+leaky+LN, GEMM4(tf32)+leaky+LN ----------------
// 32 graphs / block, 128 blocks, 256 threads, 64-row W k-tiles, 2 CTAs/SM.
#define FIN_SMEM_FLOATS (4224 + 4224 + 8704 + 8704 + 128*6 + 64)

__global__ __launch_bounds__(256) void final_kernel(
    const float* __restrict__ b3,
    const float* __restrict__ g3, const float* __restrict__ be3,
    const float* __restrict__ b4,
    const float* __restrict__ g4, const float* __restrict__ be4,
    float* __restrict__ out)
{
    extern __shared__ float sm[];
    float* sAh = sm;               // 32 x 132 = 4224
    float* sAl = sAh + 4224;       // 4224
    float* sWh = sAl + 4224;       // 64 x 136 = 8704
    float* sWl = sWh + 8704;       // 8704
    float* sB3 = sWl + 8704;
    float* sG3 = sB3 + 128;
    float* sBe3= sG3 + 128;
    float* sB4 = sBe3+ 128;
    float* sG4 = sB4 + 128;
    float* sBe4= sG4 + 128;
    float* sMu = sBe4+ 128;        // 32
    float* sIs = sMu + 32;         // 32

    int t = threadIdx.x;
    int g0 = blockIdx.x * 32;
    int wid = t >> 5, lane = t & 31;
    int g = lane >> 2, t4 = lane & 3;

    if (t < 128){
        sB3[t]=b3[t]; sG3[t]=g3[t]; sBe3[t]=be3[t];
        sB4[t]=b4[t]; sG4[t]=g4[t]; sBe4[t]=be4[t];
    }

    float acc[2][2][4];
    #pragma unroll
    for (int mt = 0; mt < 2; mt++)
        #pragma unroll
        for (int jj = 0; jj < 2; jj++){
            acc[mt][jj][0]=0.f; acc[mt][jj][1]=0.f; acc[mt][jj][2]=0.f; acc[mt][jj][3]=0.f;
        }

    for (int kt = 0; kt < 16; kt++){
        __syncthreads();
        {
            #pragma unroll
            for (int e = 0; e < 2; e++){
                int i4 = t + 256*e;
                int r = i4 >> 4, c4 = i4 & 15;
                float4 a = *(const float4*)&g_outflat[(size_t)(g0 + r)*1024 + kt*64 + 4*c4];
                float4 h, l;
                h.x = tf32_rn(a.x); l.x = tf32_rn(a.x - h.x);
                h.y = tf32_rn(a.y); l.y = tf32_rn(a.y - h.y);
                h.z = tf32_rn(a.z); l.z = tf32_rn(a.z - h.z);
                h.w = tf32_rn(a.w); l.w = tf32_rn(a.w - h.w);
                *(float4*)&sAh[r*132 + 4*c4] = h;
                *(float4*)&sAl[r*132 + 4*c4] = l;
            }
        }
        {
            const float4* wh = (const float4*)(g_W3h + (size_t)kt * 64 * 128);
            const float4* wl = (const float4*)(g_W3l + (size_t)kt * 64 * 128);
            #pragma unroll
            for (int e = 0; e < 8; e++){
                int i4 = t + 256*e;
                int k = i4 >> 5, c4 = i4 & 31;
                *(float4*)&sWh[k*136 + 4*c4] = wh[i4];
                *(float4*)&sWl[k*136 + 4*c4] = wl[i4];
            }
        }
        __syncthreads();

        #pragma unroll
        for (int ks = 0; ks < 8; ks++){
            int k0 = ks * 8;
            float ah[2][4], al[2][4];
            #pragma unroll
            for (int mt = 0; mt < 2; mt++){
                int ro = (mt*16 + g)*132 + k0;
                ah[mt][0]=sAh[ro+t4];         al[mt][0]=sAl[ro+t4];
                ah[mt][1]=sAh[ro+8*132+t4];   al[mt][1]=sAl[ro+8*132+t4];
                ah[mt][2]=sAh[ro+t4+4];       al[mt][2]=sAl[ro+t4+4];
                ah[mt][3]=sAh[ro+8*132+t4+4]; al[mt][3]=sAl[ro+8*132+t4+4];
            }
            #pragma unroll
            for (int jj = 0; jj < 2; jj++){
                int kr = (k0 + t4)*136 + wid*16 + jj*8 + g;
                float bh0 = sWh[kr],         bl0 = sWl[kr];
                float bh1 = sWh[kr + 4*136], bl1 = sWl[kr + 4*136];
                #pragma unroll
                for (int mt = 0; mt < 2; mt++){
                    mma_tf32(acc[mt][jj], ah[mt][0],ah[mt][1],ah[mt][2],ah[mt][3], bh0,bh1);
                    mma_tf32(acc[mt][jj], al[mt][0],al[mt][1],al[mt][2],al[mt][3], bh0,bh1);
                    mma_tf32(acc[mt][jj], ah[mt][0],ah[mt][1],ah[mt][2],ah[mt][3], bl0,bl1);
                }
            }
        }
    }
    __syncthreads();

    {
        #pragma unroll
        for (int mt = 0; mt < 2; mt++){
            int rA = mt*16 + g, rB = rA + 8;
            #pragma unroll
            for (int jj = 0; jj < 2; jj++){
                int c = wid*16 + jj*8 + 2*t4;
                sAh[rA*132 + c]     = leaky(acc[mt][jj][0] + sB3[c]);
                sAh[rA*132 + c + 1] = leaky(acc[mt][jj][1] + sB3[c+1]);
                sAh[rB*132 + c]     = leaky(acc[mt][jj][2] + sB3[c]);
                sAh[rB*132 + c + 1] = leaky(acc[mt][jj][3] + sB3[c+1]);
            }
        }
    }
    __syncthreads();

    if (t < 32){
        float sum = 0.f, ss = 0.f;
        #pragma unroll 8
        for (int j = 0; j < 128; j++){ float v = sAh[t*132 + j]; sum += v; ss += v*v; }
        float mu = sum * (1.f/128.f);
        float var = ss * (1.f/128.f) - mu*mu;
        sMu[t] = mu; sIs[t] = rsqrtf(var + EPS);
    }
    __syncthreads();
    {
        #pragma unroll
        for (int e = 0; e < 16; e++){
            int idx = t + 256*e;
            int r = idx >> 7, c = idx & 127;
            float v = (sAh[r*132 + c] - sMu[r]) * sIs[r] * sG3[c] + sBe3[c];
            float h = tf32_rn(v);
            sAh[r*132 + c] = h;
            sAl[r*132 + c] = tf32_rn(v - h);
        }
    }

    float acc2[2][2][4];
    #pragma unroll
    for (int mt = 0; mt < 2; mt++)
        #pragma unroll
        for (int jj = 0; jj < 2; jj++){
            acc2[mt][jj][0]=0.f; acc2[mt][jj][1]=0.f; acc2[mt][jj][2]=0.f; acc2[mt][jj][3]=0.f;
        }

    for (int half = 0; half < 2; half++){
        __syncthreads();
        {
            const float4* wh = (const float4*)(g_W4h + (size_t)half * 64 * 128);
            const float4* wl = (const float4*)(g_W4l + (size_t)half * 64 * 128);
            #pragma unroll
            for (int e = 0; e < 8; e++){
                int i4 = t + 256*e;
                int k = i4 >> 5, c4 = i4 & 31;
                *(float4*)&sWh[k*136 + 4*c4] = wh[i4];
                *(float4*)&sWl[k*136 + 4*c4] = wl[i4];
            }
        }
        __syncthreads();

        #pragma unroll
        for (int ks = 0; ks < 8; ks++){
            int k0 = half*64 + ks*8;
            int kw = ks*8;
            float ah[2][4], al[2][4];
            #pragma unroll
            for (int mt = 0; mt < 2; mt++){
                int ro = (mt*16 + g)*132 + k0;
                ah[mt][0]=sAh[ro+t4];         al[mt][0]=sAl[ro+t4];
                ah[mt][1]=sAh[ro+8*132+t4];   al[mt][1]=sAl[ro+8*132+t4];
                ah[mt][2]=sAh[ro+t4+4];       al[mt][2]=sAl[ro+t4+4];
                ah[mt][3]=sAh[ro+8*132+t4+4]; al[mt][3]=sAl[ro+8*132+t4+4];
            }
            #pragma unroll
            for (int jj = 0; jj < 2; jj++){
                int kr = (kw + t4)*136 + wid*16 + jj*8 + g;
                float bh0 = sWh[kr],         bl0 = sWl[kr];
                float bh1 = sWh[kr + 4*136], bl1 = sWl[kr + 4*136];
                #pragma unroll
                for (int mt = 0; mt < 2; mt++){
                    mma_tf32(acc2[mt][jj], ah[mt][0],ah[mt][1],ah[mt][2],ah[mt][3], bh0,bh1);
                    mma_tf32(acc2[mt][jj], al[mt][0],al[mt][1],al[mt][2],al[mt][3], bh0,bh1);
                    mma_tf32(acc2[mt][jj], ah[mt][0],ah[mt][1],ah[mt][2],ah[mt][3], bl0,bl1);
                }
            }
        }
    }
    __syncthreads();

    float* sO2 = sWh;
    #pragma unroll
    for (int mt = 0; mt < 2; mt++){
        int rA = mt*16 + g, rB = rA + 8;
        #pragma unroll
        for (int jj = 0; jj < 2; jj++){
            int c = wid*16 + jj*8 + 2*t4;
            sO2[rA*132 + c]     = leaky(acc2[mt][jj][0] + sB4[c]);
            sO2[rA*132 + c + 1] = leaky(acc2[mt][jj][1] + sB4[c+1]);
            sO2[rB*132 + c]     = leaky(acc2[mt][jj][2] + sB4[c]);
            sO2[rB*132 + c + 1] = leaky(acc2[mt][jj][3] + sB4[c+1]);
        }
    }
    __syncthreads();

    if (t < 32){
        float sum = 0.f, ss = 0.f;
        #pragma unroll 8
        for (int j = 0; j < 128; j++){ float v = sO2[t*132 + j]; sum += v; ss += v*v; }
        float mu = sum * (1.f/128.f);
        float var = ss * (1.f/128.f) - mu*mu;
        sMu[t] = mu; sIs[t] = rsqrtf(var + EPS);
    }
    __syncthreads();
    #pragma unroll
    for (int e = 0; e < 16; e++){
        int idx = t + 256*e;
        int r = idx >> 7, c = idx & 127;
        out[(g0 + r)*128 + c] = (sO2[r*132 + c] - sMu[r]) * sIs[r] * sG4[c] + sBe4[c];
    }
}

// ---------------- host ----------------
extern "C" void kernel_launch(void* const* d_in, const int* in_sizes, int n_in,
                              void* d_out, int out_size)
{
    const float* feat = (const float*)d_in[0];
    const int*   batch = (const int*)d_in[1];
    const float* W1 = (const float*)d_in[2];
    const float* b1 = (const float*)d_in[3];
    const float* g1 = (const float*)d_in[4];
    const float* be1= (const float*)d_in[5];
    const float* W2 = (const float*)d_in[6];
    const float* b2 = (const float*)d_in[7];
    const float* W3 = (const float*)d_in[8];
    const float* b3 = (const float*)d_in[9];
    const float* g3 = (const float*)d_in[10];
    const float* be3= (const float*)d_in[11];
    const float* W4 = (const float*)d_in[12];
    const float* b4 = (const float*)d_in[13];
    const float* g4 = (const float*)d_in[14];
    const float* be4= (const float*)d_in[15];

    int nrows = in_sizes[0] / 128;

    const int att_smem = ATT_SMEM_FLOATS * (int)sizeof(float);   // 110,880 B -> 2 CTAs/SM
    const int fin_smem = FIN_SMEM_FLOATS * (int)sizeof(float);   // 106,752 B -> 2 CTAs/SM
    cudaFuncSetAttribute(att_kernel,   cudaFuncAttributeMaxDynamicSharedMemorySize, att_smem);
    cudaFuncSetAttribute(final_kernel, cudaFuncAttributeMaxDynamicSharedMemorySize, fin_smem);

    detect_kernel<<<1, 256>>>(batch, nrows);
    prep_kernel<<<576, 256>>>(W3, W4);
    att_kernel<<<nrows / 64, 256, att_smem>>>(feat, W1, b1, g1, be1, W2, b2);
    aggregate_kernel<<<NGRAPH, 256>>>(feat, batch, nrows);
    final_kernel<<<NGRAPH / 32, 256, fin_smem>>>(b3, g3, be3, b4, g4, be4, (float*)d_out);
}

// round 9
// speedup vs baseline: 1.0735x; 1.0735x over previous
#include <cuda_runtime.h>
#include <cstdint>

#define NGRAPH 4096
#define EPS 1e-6f

// ---------------- device scratch ----------------
__device__ __align__(16) float g_att[262144 * 8];          // exp attention, unnormalized [N,8]
__device__ __align__(16) float g_outflat[NGRAPH * 1024];   // aggregated [B, H*D]
__device__ __align__(16) float g_inv[NGRAPH * 8];          // 1 / segment softmax denom
__device__ int g_seglo[NGRAPH + 1];                        // segment start offsets
__device__ int g_is64;                                     // batch dtype flag

__device__ __forceinline__ float leaky(float x){ return x > 0.f ? x : 0.01f * x; }

__device__ __forceinline__ float tf32_rn(float x){
    uint32_t u;
    asm("cvt.rna.tf32.f32 %0, %1;" : "=r"(u) : "f"(x));
    return __uint_as_float(u);
}

// D += A(16x8 tf32) * B(8x8 tf32), fp32 accumulate
__device__ __forceinline__ void mma_tf32(float* c,
    float a0, float a1, float a2, float a3, float b0, float b1){
    asm volatile(
      "mma.sync.aligned.m16n8k8.row.col.f32.tf32.tf32.f32 "
      "{%0,%1,%2,%3}, {%4,%5,%6,%7}, {%8,%9}, {%0,%1,%2,%3};\n"
      : "+f"(c[0]), "+f"(c[1]), "+f"(c[2]), "+f"(c[3])
      : "r"(__float_as_uint(a0)), "r"(__float_as_uint(a1)),
        "r"(__float_as_uint(a2)), "r"(__float_as_uint(a3)),
        "r"(__float_as_uint(b0)), "r"(__float_as_uint(b1)));
}

// Parallel batch dtype detection (int32 loads only).
__global__ void detect_kernel(const int* __restrict__ batch, int n){
    __shared__ int bad;
    if (threadIdx.x == 0) bad = 0;
    __syncthreads();
    int base = n / 2;
    int i = threadIdx.x;
    int lo = batch[base + 2*i];
    int hi = batch[base + 2*i + 1];
    if (hi != 0 || lo < 0 || lo >= NGRAPH) bad = 1;
    __syncthreads();
    if (threadIdx.x == 0) g_is64 = (bad == 0);
}

__device__ __forceinline__ int bat(const int* b, int i, int is64){
    return is64 ? b[2*i] : b[i];
}

__device__ __forceinline__ int lbound(const int* b, int n, int val, int is64){
    int lo = 0, hi = n;
    while (lo < hi){
        int mid = (lo + hi) >> 1;
        if (bat(b, mid, is64) < val) lo = mid + 1; else hi = mid;
    }
    return lo;
}

// ---------------- segment bounds: one thread per graph ----------------
__global__ void bounds_kernel(const int* __restrict__ batch, int n){
    int g = blockIdx.x * 256 + threadIdx.x;
    int is64 = g_is64;
    if (g < NGRAPH) g_seglo[g] = lbound(batch, n, g, is64);
    if (g == 0)     g_seglo[NGRAPH] = n;
}

// ---------------- softmax denominators: one warp per graph ----------------
// lane = rr*8 + h; rows strided by 4; reduce over rr via shfl.
__global__ void sums_kernel(int n){
    int w = (blockIdx.x * 256 + threadIdx.x) >> 5;   // graph id (4096 warps)
    int lane = threadIdx.x & 31;
    int rr = lane >> 3, h = lane & 7;
    int lo = g_seglo[w], hi = g_seglo[w + 1];
    float s = 0.f;
    for (int r = lo + rr; r < hi; r += 4) s += g_att[(size_t)r*8 + h];
    s += __shfl_xor_sync(0xffffffffu, s, 8);
    s += __shfl_xor_sync(0xffffffffu, s, 16);
    if (lane < 8) g_inv[w*8 + lane] = (hi > lo) ? 1.f / s : 0.f;
}

// ---------------- Pass A: fused GEMM1(tf32 mma) + leaky + LN + GEMM2 + exp ----------------
// 128 rows / block, 256 threads (8 warps, one 16-row M-tile each), 2048 blocks.
#define AS 132              // sA row stride
#define WS 68               // sW1 row stride
#define ATT_SMEM_FLOATS (16896 + 8704 + 512 + 64*3 + 8 + 256)

__global__ __launch_bounds__(256) void att_kernel(
    const float* __restrict__ feat,
    const float* __restrict__ W1, const float* __restrict__ b1,
    const float* __restrict__ g1, const float* __restrict__ be1,
    const float* __restrict__ W2, const float* __restrict__ b2)
{
    extern __shared__ float sm[];
    float* sA  = sm;                 // 128 x 132 = 16896 (aliased later as sH stride 65)
    float* sW1 = sA  + 16896;        // 128 x 68  = 8704
    float* sW2 = sW1 + 8704;         // 512
    float* sB1 = sW2 + 512;          // 64
    float* sG1 = sB1 + 64;           // 64
    float* sBe1= sG1 + 64;           // 64
    float* sB2 = sBe1+ 64;           // 8
    float* sMu = sB2 + 8;            // 128
    float* sIs = sMu + 128;          // 128
    float* sH  = sA;                 // alias, stride 65 (8320 <= 16896)

    int t = threadIdx.x;
    int row0 = blockIdx.x * 128;
    int wid = t >> 5, lane = t & 31;
    int g = lane >> 2, t4 = lane & 3;

    {   // feat tile 128x128 -> sA stride 132
        const float4* gsrc = (const float4*)(feat + (size_t)row0 * 128);
        #pragma unroll
        for (int e = 0; e < 16; e++){
            int idx4 = t + 256*e;
            int r = idx4 >> 5, c4 = idx4 & 31;
            *(float4*)&sA[r*AS + 4*c4] = gsrc[idx4];
        }
    }
    {   // W1 128x64 -> sW1 stride 68
        const float4* gsrc = (const float4*)W1;
        #pragma unroll
        for (int e = 0; e < 8; e++){
            int idx4 = t + 256*e;
            int k = idx4 >> 4, c4 = idx4 & 15;
            *(float4*)&sW1[k*WS + 4*c4] = gsrc[idx4];
        }
    }
    if (t < 128) ((float4*)sW2)[t] = ((const float4*)W2)[t];
    if (t < 64){ sB1[t] = b1[t]; sG1[t] = g1[t]; sBe1[t] = be1[t]; }
    if (t < 8)  sB2[t] = b2[t];
    __syncthreads();

    // GEMM1 via tf32 split mma: each warp = 16 rows x 64 cols
    int rbase = wid * 16;
    float acc[8][4];
    #pragma unroll
    for (int j = 0; j < 8; j++){ acc[j][0]=acc[j][1]=acc[j][2]=acc[j][3]=0.f; }

    const float* A0 = sA + (rbase + g) * AS;
    const float* A1 = A0 + 8 * AS;

    #pragma unroll 4
    for (int ks = 0; ks < 16; ks++){
        int k0 = ks * 8;
        float a0 = A0[k0+t4],   a1 = A1[k0+t4];
        float a2 = A0[k0+t4+4], a3 = A1[k0+t4+4];
        float ah0=tf32_rn(a0), ah1=tf32_rn(a1), ah2=tf32_rn(a2), ah3=tf32_rn(a3);
        float al0=tf32_rn(a0-ah0), al1=tf32_rn(a1-ah1), al2=tf32_rn(a2-ah2), al3=tf32_rn(a3-ah3);
        const float* Bk = sW1 + (k0 + t4) * WS + g;
        #pragma unroll
        for (int j = 0; j < 8; j++){
            float b0 = Bk[j*8];
            float b1 = Bk[4*WS + j*8];
            float bh0 = tf32_rn(b0), bh1 = tf32_rn(b1);
            float bl0 = tf32_rn(b0-bh0), bl1 = tf32_rn(b1-bh1);
            mma_tf32(acc[j], ah0,ah1,ah2,ah3, bh0,bh1);
            mma_tf32(acc[j], al0,al1,al2,al3, bh0,bh1);
            mma_tf32(acc[j], ah0,ah1,ah2,ah3, bl0,bl1);
        }
    }
    __syncthreads();   // all sA reads complete before aliasing as sH

    {   // epilogue: bias + leaky -> sH (stride 65)
        int rA = rbase + g, rB = rA + 8;
        #pragma unroll
        for (int j = 0; j < 8; j++){
            int c = j*8 + 2*t4;
            sH[rA*65 + c]     = leaky(acc[j][0] + sB1[c]);
            sH[rA*65 + c + 1] = leaky(acc[j][1] + sB1[c+1]);
            sH[rB*65 + c]     = leaky(acc[j][2] + sB1[c]);
            sH[rB*65 + c + 1] = leaky(acc[j][3] + sB1[c+1]);
        }
    }
    __syncthreads();

    if (t < 128){   // LN stats per row
        float sum = 0.f, ss = 0.f;
        #pragma unroll 8
        for (int j = 0; j < 64; j++){ float v = sH[t*65 + j]; sum += v; ss += v*v; }
        float mu = sum * (1.f/64.f);
        float var = ss * (1.f/64.f) - mu*mu;
        sMu[t] = mu; sIs[t] = rsqrtf(var + EPS);
    }
    __syncthreads();

    {   // GEMM2 (64->8) + exp, 2 threads per row x 4 outputs
        int row = t >> 1, half = t & 1, kb = half * 4;
        float mu = sMu[row], is = sIs[row];
        float a0=0.f, a1=0.f, a2=0.f, a3=0.f;
        #pragma unroll 4
        for (int j = 0; j < 64; j++){
            float hn = (sH[row*65 + j] - mu) * is * sG1[j] + sBe1[j];
            a0 += hn * sW2[j*8 + kb + 0];
            a1 += hn * sW2[j*8 + kb + 1];
            a2 += hn * sW2[j*8 + kb + 2];
            a3 += hn * sW2[j*8 + kb + 3];
        }
        int grow = row0 + row;
        float4 o;
        o.x = __expf(a0 + sB2[kb+0]);
        o.y = __expf(a1 + sB2[kb+1]);
        o.z = __expf(a2 + sB2[kb+2]);
        o.w = __expf(a3 + sB2[kb+3]);
        *(float4*)&g_att[grow*8 + kb] = o;
    }
}

// ---------------- Pass B: block-per-graph streaming aggregation ----------------
// 4096 blocks x 128 threads, no smem, no syncs. Thread owns column c = tid;
// streams all rows of its graph; att rows are uniform (broadcast) loads.
__global__ __launch_bounds__(128) void aggregate_kernel(const float* __restrict__ feat){
    int gi = blockIdx.x;
    int c = threadIdx.x;
    int lo = g_seglo[gi], hi = g_seglo[gi + 1];

    float acc[8];
    #pragma unroll
    for (int h = 0; h < 8; h++) acc[h] = 0.f;

    #pragma unroll 4
    for (int r = lo; r < hi; r++){
        float f = feat[(size_t)r * 128 + c];
        float4 a0 = *(const float4*)&g_att[(size_t)r * 8];      // uniform
        float4 a1 = *(const float4*)&g_att[(size_t)r * 8 + 4];
        acc[0] += a0.x * f; acc[1] += a0.y * f;
        acc[2] += a0.z * f; acc[3] += a0.w * f;
        acc[4] += a1.x * f; acc[5] += a1.y * f;
        acc[6] += a1.z * f; acc[7] += a1.w * f;
    }

    #pragma unroll
    for (int h = 0; h < 8; h++)
        g_outflat[(size_t)gi*1024 + h*128 + c] = acc[h] * g_inv[gi*8 + h];
}

// ---------------- Pass C: GEMM3(tf32)+leaky+LN, GEMM4(tf32)+leaky+LN ----------------
// 16 graphs / block, 256 blocks, 256 threads (R5-measured 51.1 us version).
#define FS 132
#define FIN_SMEM_FLOATS (2112 + 16896 + 128*6 + 32)

__global__ __launch_bounds__(256) void final_kernel(
    const float* __restrict__ W3, const float* __restrict__ b3,
    const float* __restrict__ g3, const float* __restrict__ be3,
    const float* __restrict__ W4, const float* __restrict__ b4,
    const float* __restrict__ g4, const float* __restrict__ be4,
    float* __restrict__ out)
{
    extern __shared__ float sm[];
    float* sA  = sm;                 // 16 x 132 = 2112 (aliased as sO1)
    float* sW  = sA + 2112;          // 128 x 132 = 16896 (W3 tile -> W4 -> sO2)
    float* sB3 = sW + 16896;
    float* sG3 = sB3 + 128;
    float* sBe3= sG3 + 128;
    float* sB4 = sBe3+ 128;
    float* sG4 = sB4 + 128;
    float* sBe4= sG4 + 128;
    float* sMu = sBe4+ 128;          // 16
    float* sIs = sMu + 16;           // 16

    int t = threadIdx.x;
    int g0 = blockIdx.x * 16;
    int wid = t >> 5, lane = t & 31;
    int g = lane >> 2, t4 = lane & 3;

    if (t < 128){
        sB3[t]=b3[t]; sG3[t]=g3[t]; sBe3[t]=be3[t];
        sB4[t]=b4[t]; sG4[t]=g4[t]; sBe4[t]=be4[t];
    }

    // ---- GEMM3: [16,1024] @ [1024,128], 8 k-tiles of 128 ----
    float acc[2][4];
    acc[0][0]=acc[0][1]=acc[0][2]=acc[0][3]=0.f;
    acc[1][0]=acc[1][1]=acc[1][2]=acc[1][3]=0.f;

    for (int kt = 0; kt < 8; kt++){
        __syncthreads();
        {   // stage A: 16 x 128 (512 float4)
            #pragma unroll
            for (int e = 0; e < 2; e++){
                int i4 = t + 256*e;
                if (i4 < 512){
                    int r = i4 >> 5, c4 = i4 & 31;
                    *(float4*)&sA[r*FS + 4*c4] =
                        *(const float4*)&g_outflat[(size_t)(g0 + r)*1024 + kt*128 + 4*c4];
                }
            }
        }
        {   // stage W3 k-tile: 128 x 128 (4096 float4)
            const float* wsrc = W3 + (size_t)kt * 128 * 128;
            #pragma unroll
            for (int e = 0; e < 16; e++){
                int i4 = t + 256*e;
                int r = i4 >> 5, c4 = i4 & 31;
                *(float4*)&sW[r*FS + 4*c4] = *(const float4*)&wsrc[r*128 + 4*c4];
            }
        }
        __syncthreads();

        const float* A0 = sA + g * FS;
        const float* A1 = sA + (g + 8) * FS;
        #pragma unroll 4
        for (int ks = 0; ks < 16; ks++){
            int k0 = ks * 8;
            float a0 = A0[k0+t4],   a1 = A1[k0+t4];
            float a2 = A0[k0+t4+4], a3 = A1[k0+t4+4];
            float ah0=tf32_rn(a0), ah1=tf32_rn(a1), ah2=tf32_rn(a2), ah3=tf32_rn(a3);
            float al0=tf32_rn(a0-ah0), al1=tf32_rn(a1-ah1), al2=tf32_rn(a2-ah2), al3=tf32_rn(a3-ah3);
            const float* Bk = sW + (k0 + t4) * FS + wid*16 + g;
            #pragma unroll
            for (int jj = 0; jj < 2; jj++){
                float b0 = Bk[jj*8];
                float b1 = Bk[4*FS + jj*8];
                float bh0 = tf32_rn(b0), bh1 = tf32_rn(b1);
                float bl0 = tf32_rn(b0-bh0), bl1 = tf32_rn(b1-bh1);
                mma_tf32(acc[jj], ah0,ah1,ah2,ah3, bh0,bh1);
                mma_tf32(acc[jj], al0,al1,al2,al3, bh0,bh1);
                mma_tf32(acc[jj], ah0,ah1,ah2,ah3, bl0,bl1);
            }
        }
    }
    __syncthreads();

    float* sO1 = sA;   // 16 x 132 alias
    {   // epilogue GEMM3 -> sO1; stage W4 -> sW
        #pragma unroll
        for (int jj = 0; jj < 2; jj++){
            int c = wid*16 + jj*8 + 2*t4;
            sO1[g*FS + c]       = leaky(acc[jj][0] + sB3[c]);
            sO1[g*FS + c + 1]   = leaky(acc[jj][1] + sB3[c+1]);
            sO1[(g+8)*FS + c]   = leaky(acc[jj][2] + sB3[c]);
            sO1[(g+8)*FS + c+1] = leaky(acc[jj][3] + sB3[c+1]);
        }
        #pragma unroll
        for (int e = 0; e < 16; e++){
            int i4 = t + 256*e;
            int r = i4 >> 5, c4 = i4 & 31;
            *(float4*)&sW[r*FS + 4*c4] = *(const float4*)&W4[r*128 + 4*c4];
        }
    }
    __syncthreads();

    if (t < 16){   // LN1 stats
        float sum = 0.f, ss = 0.f;
        #pragma unroll 8
        for (int j = 0; j < 128; j++){ float v = sO1[t*FS + j]; sum += v; ss += v*v; }
        float mu = sum * (1.f/128.f);
        float var = ss * (1.f/128.f) - mu*mu;
        sMu[t] = mu; sIs[t] = rsqrtf(var + EPS);
    }
    __syncthreads();
    #pragma unroll
    for (int e = 0; e < 8; e++){
        int idx = t + 256*e;
        int r = idx >> 7, c = idx & 127;
        sO1[r*FS + c] = (sO1[r*FS + c] - sMu[r]) * sIs[r] * sG3[c] + sBe3[c];
    }
    __syncthreads();

    // ---- GEMM4: [16,128] @ [128,128] ----
    float acc2[2][4];
    acc2[0][0]=acc2[0][1]=acc2[0][2]=acc2[0][3]=0.f;
    acc2[1][0]=acc2[1][1]=acc2[1][2]=acc2[1][3]=0.f;
    {
        const float* A0 = sO1 + g * FS;
        const float* A1 = sO1 + (g + 8) * FS;
        #pragma unroll 4
        for (int ks = 0; ks < 16; ks++){
            int k0 = ks * 8;
            float a0 = A0[k0+t4],   a1 = A1[k0+t4];
            float a2 = A0[k0+t4+4], a3 = A1[k0+t4+4];
            float ah0=tf32_rn(a0), ah1=tf32_rn(a1), ah2=tf32_rn(a2), ah3=tf32_rn(a3);
            float al0=tf32_rn(a0-ah0), al1=tf32_rn(a1-ah1), al2=tf32_rn(a2-ah2), al3=tf32_rn(a3-ah3);
            const float* Bk = sW + (k0 + t4) * FS + wid*16 + g;
            #pragma unroll
            for (int jj = 0; jj < 2; jj++){
                float b0 = Bk[jj*8];
                float b1 = Bk[4*FS + jj*8];
                float bh0 = tf32_rn(b0), bh1 = tf32_rn(b1);
                float bl0 = tf32_rn(b0-bh0), bl1 = tf32_rn(b1-bh1);
                mma_tf32(acc2[jj], ah0,ah1,ah2,ah3, bh0,bh1);
                mma_tf32(acc2[jj], al0,al1,al2,al3, bh0,bh1);
                mma_tf32(acc2[jj], ah0,ah1,ah2,ah3, bl0,bl1);
            }
        }
    }
    __syncthreads();   // all sW (W4) reads done

    float* sO2 = sW;   // 16 x 132 alias inside W4 region
    #pragma unroll
    for (int jj = 0; jj < 2; jj++){
        int c = wid*16 + jj*8 + 2*t4;
        sO2[g*FS + c]       = leaky(acc2[jj][0] + sB4[c]);
        sO2[g*FS + c + 1]   = leaky(acc2[jj][1] + sB4[c+1]);
        sO2[(g+8)*FS + c]   = leaky(acc2[jj][2] + sB4[c]);
        sO2[(g+8)*FS + c+1] = leaky(acc2[jj][3] + sB4[c+1]);
    }
    __syncthreads();

    if (t < 16){   // LN2 stats
        float sum = 0.f, ss = 0.f;
        #pragma unroll 8
        for (int j = 0; j < 128; j++){ float v = sO2[t*FS + j]; sum += v; ss += v*v; }
        float mu = sum * (1.f/128.f);
        float var = ss * (1.f/128.f) - mu*mu;
        sMu[t] = mu; sIs[t] = rsqrtf(var + EPS);
    }
    __syncthreads();
    #pragma unroll
    for (int e = 0; e < 8; e++){
        int idx = t + 256*e;
        int r = idx >> 7, c = idx & 127;
        out[(g0 + r)*128 + c] = (sO2[r*FS + c] - sMu[r]) * sIs[r] * sG4[c] + sBe4[c];
    }
}

// ---------------- host ----------------
extern "C" void kernel_launch(void* const* d_in, const int* in_sizes, int n_in,
                              void* d_out, int out_size)
{
    const float* feat = (const float*)d_in[0];
    const int*   batch = (const int*)d_in[1];
    const float* W1 = (const float*)d_in[2];
    const float* b1 = (const float*)d_in[3];
    const float* g1 = (const float*)d_in[4];
    const float* be1= (const float*)d_in[5];
    const float* W2 = (const float*)d_in[6];
    const float* b2 = (const float*)d_in[7];
    const float* W3 = (const float*)d_in[8];
    const float* b3 = (const float*)d_in[9];
    const float* g3 = (const float*)d_in[10];
    const float* be3= (const float*)d_in[11];
    const float* W4 = (const float*)d_in[12];
    const float* b4 = (const float*)d_in[13];
    const float* g4 = (const float*)d_in[14];
    const float* be4= (const float*)d_in[15];

    int nrows = in_sizes[0] / 128;

    const int att_smem = ATT_SMEM_FLOATS * (int)sizeof(float);   // 106.3 KB -> 2 CTAs/SM
    const int fin_smem = FIN_SMEM_FLOATS * (int)sizeof(float);   //  93.4 KB -> 2 CTAs/SM
    cudaFuncSetAttribute(att_kernel,   cudaFuncAttributeMaxDynamicSharedMemorySize, att_smem);
    cudaFuncSetAttribute(final_kernel, cudaFuncAttributeMaxDynamicSharedMemorySize, fin_smem);

    detect_kernel<<<1, 256>>>(batch, nrows);
    bounds_kernel<<<NGRAPH / 256, 256>>>(batch, nrows);
    att_kernel<<<nrows / 128, 256, att_smem>>>(feat, W1, b1, g1, be1, W2, b2);
    sums_kernel<<<NGRAPH / 8, 256>>>(nrows);
    aggregate_kernel<<<NGRAPH, 128>>>(feat);
    final_kernel<<<NGRAPH / 16, 256, fin_smem>>>(W3, b3, g3, be3, W4, b4, g4, be4, (float*)d_out);
}

// round 10
// speedup vs baseline: 1.1826x; 1.1017x over previous
#include <cuda_runtime.h>
#include <cstdint>

#define NGRAPH 4096
#define EPS 1e-6f

// ---------------- device scratch ----------------
__device__ __align__(16) float g_att[262144 * 8];          // exp attention, unnormalized [N,8]
__device__ __align__(16) float g_outflat[NGRAPH * 1024];   // aggregated [B, H*D]
__device__ int g_is64;                                     // batch dtype flag

__device__ __forceinline__ float leaky(float x){ return x > 0.f ? x : 0.01f * x; }

__device__ __forceinline__ float tf32_rn(float x){
    uint32_t u;
    asm("cvt.rna.tf32.f32 %0, %1;" : "=r"(u) : "f"(x));
    return __uint_as_float(u);
}

// D += A(16x8 tf32) * B(8x8 tf32), fp32 accumulate
__device__ __forceinline__ void mma_tf32(float* c,
    float a0, float a1, float a2, float a3, float b0, float b1){
    asm volatile(
      "mma.sync.aligned.m16n8k8.row.col.f32.tf32.tf32.f32 "
      "{%0,%1,%2,%3}, {%4,%5,%6,%7}, {%8,%9}, {%0,%1,%2,%3};\n"
      : "+f"(c[0]), "+f"(c[1]), "+f"(c[2]), "+f"(c[3])
      : "r"(__float_as_uint(a0)), "r"(__float_as_uint(a1)),
        "r"(__float_as_uint(a2)), "r"(__float_as_uint(a3)),
        "r"(__float_as_uint(b0)), "r"(__float_as_uint(b1)));
}

// Parallel batch dtype detection (int32 loads only; one load pair per thread).
__global__ void detect_kernel(const int* __restrict__ batch, int n){
    __shared__ int bad;
    if (threadIdx.x == 0) bad = 0;
    __syncthreads();
    int base = n / 2;                       // middle under int32 view
    int i = threadIdx.x;
    int lo = batch[base + 2*i];
    int hi = batch[base + 2*i + 1];
    if (hi != 0 || lo < 0 || lo >= NGRAPH) bad = 1;
    __syncthreads();
    if (threadIdx.x == 0) g_is64 = (bad == 0);
}

__device__ __forceinline__ int bat(const int* b, int i, int is64){
    return is64 ? b[2*i] : b[i];
}

__device__ __forceinline__ int lbound(const int* b, int n, int val, int is64){
    int lo = 0, hi = n;
    while (lo < hi){
        int mid = (lo + hi) >> 1;
        if (bat(b, mid, is64) < val) lo = mid + 1; else hi = mid;
    }
    return lo;
}

// ---------------- Pass A: fused GEMM1(tf32 mma) + leaky + LN + GEMM2 + exp ----------------
// 128 rows / block, 256 threads (8 warps, one 16-row M-tile each), 2048 blocks.
// (R5-measured ~28 us version, verbatim.)
#define AS 132              // sA row stride
#define WS 68               // sW1 row stride
#define ATT_SMEM_FLOATS (16896 + 8704 + 512 + 64*3 + 8 + 256)

__global__ __launch_bounds__(256) void att_kernel(
    const float* __restrict__ feat,
    const float* __restrict__ W1, const float* __restrict__ b1,
    const float* __restrict__ g1, const float* __restrict__ be1,
    const float* __restrict__ W2, const float* __restrict__ b2)
{
    extern __shared__ float sm[];
    float* sA  = sm;                 // 128 x 132 = 16896 (aliased later as sH stride 65)
    float* sW1 = sA  + 16896;        // 128 x 68  = 8704
    float* sW2 = sW1 + 8704;         // 512
    float* sB1 = sW2 + 512;          // 64
    float* sG1 = sB1 + 64;           // 64
    float* sBe1= sG1 + 64;           // 64
    float* sB2 = sBe1+ 64;           // 8
    float* sMu = sB2 + 8;            // 128
    float* sIs = sMu + 128;          // 128
    float* sH  = sA;                 // alias, stride 65 (8320 <= 16896)

    int t = threadIdx.x;
    int row0 = blockIdx.x * 128;
    int wid = t >> 5, lane = t & 31;
    int g = lane >> 2, t4 = lane & 3;

    {   // feat tile 128x128 -> sA stride 132
        const float4* gsrc = (const float4*)(feat + (size_t)row0 * 128);
        #pragma unroll
        for (int e = 0; e < 16; e++){
            int idx4 = t + 256*e;
            int r = idx4 >> 5, c4 = idx4 & 31;
            *(float4*)&sA[r*AS + 4*c4] = gsrc[idx4];
        }
    }
    {   // W1 128x64 -> sW1 stride 68
        const float4* gsrc = (const float4*)W1;
        #pragma unroll
        for (int e = 0; e < 8; e++){
            int idx4 = t + 256*e;
            int k = idx4 >> 4, c4 = idx4 & 15;
            *(float4*)&sW1[k*WS + 4*c4] = gsrc[idx4];
        }
    }
    if (t < 128) ((float4*)sW2)[t] = ((const float4*)W2)[t];
    if (t < 64){ sB1[t] = b1[t]; sG1[t] = g1[t]; sBe1[t] = be1[t]; }
    if (t < 8)  sB2[t] = b2[t];
    __syncthreads();

    // GEMM1 via tf32 split mma: each warp = 16 rows x 64 cols
    int rbase = wid * 16;
    float acc[8][4];
    #pragma unroll
    for (int j = 0; j < 8; j++){ acc[j][0]=acc[j][1]=acc[j][2]=acc[j][3]=0.f; }

    const float* A0 = sA + (rbase + g) * AS;
    const float* A1 = A0 + 8 * AS;

    #pragma unroll 4
    for (int ks = 0; ks < 16; ks++){
        int k0 = ks * 8;
        float a0 = A0[k0+t4],   a1 = A1[k0+t4];
        float a2 = A0[k0+t4+4], a3 = A1[k0+t4+4];
        float ah0=tf32_rn(a0), ah1=tf32_rn(a1), ah2=tf32_rn(a2), ah3=tf32_rn(a3);
        float al0=tf32_rn(a0-ah0), al1=tf32_rn(a1-ah1), al2=tf32_rn(a2-ah2), al3=tf32_rn(a3-ah3);
        const float* Bk = sW1 + (k0 + t4) * WS + g;
        #pragma unroll
        for (int j = 0; j < 8; j++){
            float b0 = Bk[j*8];
            float b1 = Bk[4*WS + j*8];
            float bh0 = tf32_rn(b0), bh1 = tf32_rn(b1);
            float bl0 = tf32_rn(b0-bh0), bl1 = tf32_rn(b1-bh1);
            mma_tf32(acc[j], ah0,ah1,ah2,ah3, bh0,bh1);
            mma_tf32(acc[j], al0,al1,al2,al3, bh0,bh1);
            mma_tf32(acc[j], ah0,ah1,ah2,ah3, bl0,bl1);
        }
    }
    __syncthreads();   // all sA reads complete before aliasing as sH

    {   // epilogue: bias + leaky -> sH (stride 65)
        int rA = rbase + g, rB = rA + 8;
        #pragma unroll
        for (int j = 0; j < 8; j++){
            int c = j*8 + 2*t4;
            sH[rA*65 + c]     = leaky(acc[j][0] + sB1[c]);
            sH[rA*65 + c + 1] = leaky(acc[j][1] + sB1[c+1]);
            sH[rB*65 + c]     = leaky(acc[j][2] + sB1[c]);
            sH[rB*65 + c + 1] = leaky(acc[j][3] + sB1[c+1]);
        }
    }
    __syncthreads();

    if (t < 128){   // LN stats per row
        float sum = 0.f, ss = 0.f;
        #pragma unroll 8
        for (int j = 0; j < 64; j++){ float v = sH[t*65 + j]; sum += v; ss += v*v; }
        float mu = sum * (1.f/64.f);
        float var = ss * (1.f/64.f) - mu*mu;
        sMu[t] = mu; sIs[t] = rsqrtf(var + EPS);
    }
    __syncthreads();

    {   // GEMM2 (64->8) + exp, 2 threads per row x 4 outputs
        int row = t >> 1, half = t & 1, kb = half * 4;
        float mu = sMu[row], is = sIs[row];
        float a0=0.f, a1=0.f, a2=0.f, a3=0.f;
        #pragma unroll 4
        for (int j = 0; j < 64; j++){
            float hn = (sH[row*65 + j] - mu) * is * sG1[j] + sBe1[j];
            a0 += hn * sW2[j*8 + kb + 0];
            a1 += hn * sW2[j*8 + kb + 1];
            a2 += hn * sW2[j*8 + kb + 2];
            a3 += hn * sW2[j*8 + kb + 3];
        }
        int grow = row0 + row;
        float4 o;
        o.x = __expf(a0 + sB2[kb+0]);
        o.y = __expf(a1 + sB2[kb+1]);
        o.z = __expf(a2 + sB2[kb+2]);
        o.w = __expf(a3 + sB2[kb+3]);
        *(float4*)&g_att[grow*8 + kb] = o;
    }
}

// ---------------- Pass B: single-pass segment softmax + aggregation ----------------
// (R6-measured 66.2 us version, verbatim: block-per-graph, 32-row smem tiles,
// ssum accumulated in the same pass, normalize at the end.)
__global__ __launch_bounds__(256) void aggregate_kernel(
    const float* __restrict__ feat, const int* __restrict__ batchp, int nrows)
{
    int gi = blockIdx.x;
    __shared__ int s_lo, s_hi;
    __shared__ __align__(16) float sF[32][128];
    __shared__ __align__(16) float sAtt[32][8];

    int is64 = g_is64;
    int t = threadIdx.x;
    if (t == 0)  s_lo = lbound(batchp, nrows, gi, is64);
    if (t == 32) s_hi = lbound(batchp, nrows, gi + 1, is64);
    __syncthreads();
    int lo = s_lo, hi = s_hi;
    int h = t >> 5, lane = t & 31;

    float4 acc = make_float4(0.f, 0.f, 0.f, 0.f);
    float ssum = 0.f;

    for (int base = lo; base < hi; base += 32){
        int cnt = min(32, hi - base);
        __syncthreads();
        for (int idx4 = t; idx4 < cnt*32; idx4 += 256){
            int r = idx4 >> 5, c4 = idx4 & 31;
            *(float4*)&sF[r][4*c4] = *(const float4*)&feat[(size_t)(base + r) * 128 + 4*c4];
        }
        if (t < cnt*8){
            int r = t >> 3, k = t & 7;
            sAtt[r][k] = g_att[(base + r)*8 + k];
        }
        __syncthreads();
        for (int r = 0; r < cnt; r++){
            float a = sAtt[r][h];
            ssum += a;
            float4 f = *(const float4*)&sF[r][lane*4];
            acc.x += a*f.x; acc.y += a*f.y; acc.z += a*f.z; acc.w += a*f.w;
        }
    }
    float inv = (hi > lo) ? 1.f / ssum : 0.f;
    acc.x *= inv; acc.y *= inv; acc.z *= inv; acc.w *= inv;
    *(float4*)&g_outflat[gi*1024 + h*128 + lane*4] = acc;
}

// ---------------- Pass C: GEMM3(tf32)+leaky+LN, GEMM4(tf32)+leaky+LN ----------------
// 16 graphs / block, 256 blocks, 256 threads (R5-measured 51.1 us version, verbatim).
#define FS 132
#define FIN_SMEM_FLOATS (2112 + 16896 + 128*6 + 32)

__global__ __launch_bounds__(256) void final_kernel(
    const float* __restrict__ W3, const float* __restrict__ b3,
    const float* __restrict__ g3, const float* __restrict__ be3,
    const float* __restrict__ W4, const float* __restrict__ b4,
    const float* __restrict__ g4, const float* __restrict__ be4,
    float* __restrict__ out)
{
    extern __shared__ float sm[];
    float* sA  = sm;                 // 16 x 132 = 2112 (aliased as sO1)
    float* sW  = sA + 2112;          // 128 x 132 = 16896 (W3 tile -> W4 -> sO2)
    float* sB3 = sW + 16896;
    float* sG3 = sB3 + 128;
    float* sBe3= sG3 + 128;
    float* sB4 = sBe3+ 128;
    float* sG4 = sB4 + 128;
    float* sBe4= sG4 + 128;
    float* sMu = sBe4+ 128;          // 16
    float* sIs = sMu + 16;           // 16

    int t = threadIdx.x;
    int g0 = blockIdx.x * 16;
    int wid = t >> 5, lane = t & 31;
    int g = lane >> 2, t4 = lane & 3;

    if (t < 128){
        sB3[t]=b3[t]; sG3[t]=g3[t]; sBe3[t]=be3[t];
        sB4[t]=b4[t]; sG4[t]=g4[t]; sBe4[t]=be4[t];
    }

    // ---- GEMM3: [16,1024] @ [1024,128], 8 k-tiles of 128 ----
    float acc[2][4];
    acc[0][0]=acc[0][1]=acc[0][2]=acc[0][3]=0.f;
    acc[1][0]=acc[1][1]=acc[1][2]=acc[1][3]=0.f;

    for (int kt = 0; kt < 8; kt++){
        __syncthreads();
        {   // stage A: 16 x 128 (512 float4)
            #pragma unroll
            for (int e = 0; e < 2; e++){
                int i4 = t + 256*e;
                if (i4 < 512){
                    int r = i4 >> 5, c4 = i4 & 31;
                    *(float4*)&sA[r*FS + 4*c4] =
                        *(const float4*)&g_outflat[(size_t)(g0 + r)*1024 + kt*128 + 4*c4];
                }
            }
        }
        {   // stage W3 k-tile: 128 x 128 (4096 float4)
            const float* wsrc = W3 + (size_t)kt * 128 * 128;
            #pragma unroll
            for (int e = 0; e < 16; e++){
                int i4 = t + 256*e;
                int r = i4 >> 5, c4 = i4 & 31;
                *(float4*)&sW[r*FS + 4*c4] = *(const float4*)&wsrc[r*128 + 4*c4];
            }
        }
        __syncthreads();

        const float* A0 = sA + g * FS;
        const float* A1 = sA + (g + 8) * FS;
        #pragma unroll 4
        for (int ks = 0; ks < 16; ks++){
            int k0 = ks * 8;
            float a0 = A0[k0+t4],   a1 = A1[k0+t4];
            float a2 = A0[k0+t4+4], a3 = A1[k0+t4+4];
            float ah0=tf32_rn(a0), ah1=tf32_rn(a1), ah2=tf32_rn(a2), ah3=tf32_rn(a3);
            float al0=tf32_rn(a0-ah0), al1=tf32_rn(a1-ah1), al2=tf32_rn(a2-ah2), al3=tf32_rn(a3-ah3);
            const float* Bk = sW + (k0 + t4) * FS + wid*16 + g;
            #pragma unroll
            for (int jj = 0; jj < 2; jj++){
                float b0 = Bk[jj*8];
                float b1 = Bk[4*FS + jj*8];
                float bh0 = tf32_rn(b0), bh1 = tf32_rn(b1);
                float bl0 = tf32_rn(b0-bh0), bl1 = tf32_rn(b1-bh1);
                mma_tf32(acc[jj], ah0,ah1,ah2,ah3, bh0,bh1);
                mma_tf32(acc[jj], al0,al1,al2,al3, bh0,bh1);
                mma_tf32(acc[jj], ah0,ah1,ah2,ah3, bl0,bl1);
            }
        }
    }
    __syncthreads();

    float* sO1 = sA;   // 16 x 132 alias
    {   // epilogue GEMM3 -> sO1; stage W4 -> sW
        #pragma unroll
        for (int jj = 0; jj < 2; jj++){
            int c = wid*16 + jj*8 + 2*t4;
            sO1[g*FS + c]       = leaky(acc[jj][0] + sB3[c]);
            sO1[g*FS + c + 1]   = leaky(acc[jj][1] + sB3[c+1]);
            sO1[(g+8)*FS + c]   = leaky(acc[jj][2] + sB3[c]);
            sO1[(g+8)*FS + c+1] = leaky(acc[jj][3] + sB3[c+1]);
        }
        #pragma unroll
        for (int e = 0; e < 16; e++){
            int i4 = t + 256*e;
            int r = i4 >> 5, c4 = i4 & 31;
            *(float4*)&sW[r*FS + 4*c4] = *(const float4*)&W4[r*128 + 4*c4];
        }
    }
    __syncthreads();

    if (t < 16){   // LN1 stats
        float sum = 0.f, ss = 0.f;
        #pragma unroll 8
        for (int j = 0; j < 128; j++){ float v = sO1[t*FS + j]; sum += v; ss += v*v; }
        float mu = sum * (1.f/128.f);
        float var = ss * (1.f/128.f) - mu*mu;
        sMu[t] = mu; sIs[t] = rsqrtf(var + EPS);
    }
    __syncthreads();
    #pragma unroll
    for (int e = 0; e < 8; e++){
        int idx = t + 256*e;
        int r = idx >> 7, c = idx & 127;
        sO1[r*FS + c] = (sO1[r*FS + c] - sMu[r]) * sIs[r] * sG3[c] + sBe3[c];
    }
    __syncthreads();

    // ---- GEMM4: [16,128] @ [128,128] ----
    float acc2[2][4];
    acc2[0][0]=acc2[0][1]=acc2[0][2]=acc2[0][3]=0.f;
    acc2[1][0]=acc2[1][1]=acc2[1][2]=acc2[1][3]=0.f;
    {
        const float* A0 = sO1 + g * FS;
        const float* A1 = sO1 + (g + 8) * FS;
        #pragma unroll 4
        for (int ks = 0; ks < 16; ks++){
            int k0 = ks * 8;
            float a0 = A0[k0+t4],   a1 = A1[k0+t4];
            float a2 = A0[k0+t4+4], a3 = A1[k0+t4+4];
            float ah0=tf32_rn(a0), ah1=tf32_rn(a1), ah2=tf32_rn(a2), ah3=tf32_rn(a3);
            float al0=tf32_rn(a0-ah0), al1=tf32_rn(a1-ah1), al2=tf32_rn(a2-ah2), al3=tf32_rn(a3-ah3);
            const float* Bk = sW + (k0 + t4) * FS + wid*16 + g;
            #pragma unroll
            for (int jj = 0; jj < 2; jj++){
                float b0 = Bk[jj*8];
                float b1 = Bk[4*FS + jj*8];
                float bh0 = tf32_rn(b0), bh1 = tf32_rn(b1);
                float bl0 = tf32_rn(b0-bh0), bl1 = tf32_rn(b1-bh1);
                mma_tf32(acc2[jj], ah0,ah1,ah2,ah3, bh0,bh1);
                mma_tf32(acc2[jj], al0,al1,al2,al3, bh0,bh1);
                mma_tf32(acc2[jj], ah0,ah1,ah2,ah3, bl0,bl1);
            }
        }
    }
    __syncthreads();   // all sW (W4) reads done

    float* sO2 = sW;   // 16 x 132 alias inside W4 region
    #pragma unroll
    for (int jj = 0; jj < 2; jj++){
        int c = wid*16 + jj*8 + 2*t4;
        sO2[g*FS + c]       = leaky(acc2[jj][0] + sB4[c]);
        sO2[g*FS + c + 1]   = leaky(acc2[jj][1] + sB4[c+1]);
        sO2[(g+8)*FS + c]   = leaky(acc2[jj][2] + sB4[c]);
        sO2[(g+8)*FS + c+1] = leaky(acc2[jj][3] + sB4[c+1]);
    }
    __syncthreads();

    if (t < 16){   // LN2 stats
        float sum = 0.f, ss = 0.f;
        #pragma unroll 8
        for (int j = 0; j < 128; j++){ float v = sO2[t*FS + j]; sum += v; ss += v*v; }
        float mu = sum * (1.f/128.f);
        float var = ss * (1.f/128.f) - mu*mu;
        sMu[t] = mu; sIs[t] = rsqrtf(var + EPS);
    }
    __syncthreads();
    #pragma unroll
    for (int e = 0; e < 8; e++){
        int idx = t + 256*e;
        int r = idx >> 7, c = idx & 127;
        out[(g0 + r)*128 + c] = (sO2[r*FS + c] - sMu[r]) * sIs[r] * sG4[c] + sBe4[c];
    }
}

// ---------------- host ----------------
extern "C" void kernel_launch(void* const* d_in, const int* in_sizes, int n_in,
                              void* d_out, int out_size)
{
    const float* feat = (const float*)d_in[0];
    const int*   batch = (const int*)d_in[1];
    const float* W1 = (const float*)d_in[2];
    const float* b1 = (const float*)d_in[3];
    const float* g1 = (const float*)d_in[4];
    const float* be1= (const float*)d_in[5];
    const float* W2 = (const float*)d_in[6];
    const float* b2 = (const float*)d_in[7];
    const float* W3 = (const float*)d_in[8];
    const float* b3 = (const float*)d_in[9];
    const float* g3 = (const float*)d_in[10];
    const float* be3= (const float*)d_in[11];
    const float* W4 = (const float*)d_in[12];
    const float* b4 = (const float*)d_in[13];
    const float* g4 = (const float*)d_in[14];
    const float* be4= (const float*)d_in[15];

    int nrows = in_sizes[0] / 128;

    const int att_smem = ATT_SMEM_FLOATS * (int)sizeof(float);   // 106.3 KB -> 2 CTAs/SM
    const int fin_smem = FIN_SMEM_FLOATS * (int)sizeof(float);   //  93.4 KB -> 2 CTAs/SM
    cudaFuncSetAttribute(att_kernel,   cudaFuncAttributeMaxDynamicSharedMemorySize, att_smem);
    cudaFuncSetAttribute(final_kernel, cudaFuncAttributeMaxDynamicSharedMemorySize, fin_smem);

    detect_kernel<<<1, 256>>>(batch, nrows);
    att_kernel<<<nrows / 128, 256, att_smem>>>(feat, W1, b1, g1, be1, W2, b2);
    aggregate_kernel<<<NGRAPH, 256>>>(feat, batch, nrows);
    final_kernel<<<NGRAPH / 16, 256, fin_smem>>>(W3, b3, g3, be3, W4, b4, g4, be4, (float*)d_out);
}

// round 11
// speedup vs baseline: 1.4579x; 1.2328x over previous
#include <cuda_runtime.h>
#include <cuda_bf16.h>
#include <cstdint>

#define NGRAPH 4096
#define EPS 1e-6f

// ---------------- device scratch ----------------
__device__ __align__(16) float g_att[262144 * 8];          // exp attention, unnormalized [N,8]
__device__ __align__(16) float g_outflat[NGRAPH * 1024];   // aggregated [B, H*D]
__device__ __align__(16) unsigned int g_W1h[64 * 64];      // W1 packed bf16x2 [n][kw]
__device__ __align__(16) unsigned int g_W1l[64 * 64];
__device__ __align__(16) unsigned int g_W3h[128 * 512];    // W3 packed [n][kw]
__device__ __align__(16) unsigned int g_W3l[128 * 512];
__device__ __align__(16) unsigned int g_W4h[128 * 64];     // W4 packed [n][kw]
__device__ __align__(16) unsigned int g_W4l[128 * 64];
__device__ int g_seglo[NGRAPH + 1];
__device__ int g_is64;

__device__ __forceinline__ float leaky(float x){ return x > 0.f ? x : 0.01f * x; }

// split (x,y) into bf16 hi/lo pairs packed as bf16x2 words (x in LOW half).
__device__ __forceinline__ void split2(float x, float y, uint32_t& h, uint32_t& l){
    __nv_bfloat16 hx = __float2bfloat16_rn(x);
    __nv_bfloat16 hy = __float2bfloat16_rn(y);
    float rx = x - __bfloat162float(hx);
    float ry = y - __bfloat162float(hy);
    __nv_bfloat162 hh = __halves2bfloat162(hx, hy);           // .x = low half
    __nv_bfloat162 ll = __halves2bfloat162(__float2bfloat16_rn(rx), __float2bfloat16_rn(ry));
    h = *reinterpret_cast<uint32_t*>(&hh);
    l = *reinterpret_cast<uint32_t*>(&ll);
}

// D += A(16x16 bf16) * B(16x8 bf16), fp32 accumulate
__device__ __forceinline__ void mma_bf16(float* c,
    uint32_t a0, uint32_t a1, uint32_t a2, uint32_t a3, uint32_t b0, uint32_t b1){
    asm volatile(
      "mma.sync.aligned.m16n8k16.row.col.f32.bf16.bf16.f32 "
      "{%0,%1,%2,%3}, {%4,%5,%6,%7}, {%8,%9}, {%0,%1,%2,%3};\n"
      : "+f"(c[0]), "+f"(c[1]), "+f"(c[2]), "+f"(c[3])
      : "r"(a0), "r"(a1), "r"(a2), "r"(a3), "r"(b0), "r"(b1));
}

// Parallel batch dtype detection (int32 loads only).
__global__ void detect_kernel(const int* __restrict__ batch, int n){
    __shared__ int bad;
    if (threadIdx.x == 0) bad = 0;
    __syncthreads();
    int base = n / 2;
    int i = threadIdx.x;
    int lo = batch[base + 2*i];
    int hi = batch[base + 2*i + 1];
    if (hi != 0 || lo < 0 || lo >= NGRAPH) bad = 1;
    __syncthreads();
    if (threadIdx.x == 0) g_is64 = (bad == 0);
}

__device__ __forceinline__ int bat(const int* b, int i, int is64){
    return is64 ? b[2*i] : b[i];
}

__device__ __forceinline__ int lbound(const int* b, int n, int val, int is64){
    int lo = 0, hi = n;
    while (lo < hi){
        int mid = (lo + hi) >> 1;
        if (bat(b, mid, is64) < val) lo = mid + 1; else hi = mid;
    }
    return lo;
}

// ---------------- segment bounds: one thread per graph ----------------
__global__ void bounds_kernel(const int* __restrict__ batch, int n){
    int g = blockIdx.x * 256 + threadIdx.x;
    int is64 = g_is64;
    if (g < NGRAPH) g_seglo[g] = lbound(batch, n, g, is64);
    if (g == 0)     g_seglo[NGRAPH] = n;
}

// ---------------- weight prep: pack W1/W3/W4 as bf16x2 hi/lo, [n][kword] ----------------
__global__ void prep_kernel(const float* __restrict__ W1,
                            const float* __restrict__ W3,
                            const float* __restrict__ W4){
    int idx = blockIdx.x * 256 + threadIdx.x;
    if (idx < 4096){                               // W1: [128 k][64 n] -> [64 n][64 kw]
        int n = idx >> 6, kw = idx & 63;
        uint32_t h, l;
        split2(W1[(2*kw)*64 + n], W1[(2*kw+1)*64 + n], h, l);
        g_W1h[idx] = h; g_W1l[idx] = l;
        return;
    }
    int j = idx - 4096;
    if (j < 65536){                                // W3: [1024 k][128 n] -> [128 n][512 kw]
        int n = j >> 9, kw = j & 511;
        uint32_t h, l;
        split2(W3[(2*kw)*128 + n], W3[(2*kw+1)*128 + n], h, l);
        g_W3h[j] = h; g_W3l[j] = l;
        return;
    }
    int m = j - 65536;
    if (m < 8192){                                 // W4: [128 k][128 n] -> [128 n][64 kw]
        int n = m >> 6, kw = m & 63;
        uint32_t h, l;
        split2(W4[(2*kw)*128 + n], W4[(2*kw+1)*128 + n], h, l);
        g_W4h[m] = h; g_W4l[m] = l;
    }
}

// ---------------- Pass A: GEMM1 (bf16 split mma) + leaky + LN + GEMM2 + exp ----------------
// 128 rows / block, 256 threads (8 warps, one 16-row M-tile each, full 64 cols), 2048 blocks.
// Strides (words): A 68 (bank 4g+t4), B 68 (bank 4g+t4) — both conflict-free & 16B-aligned.
#define ATT_SMEM_WORDS (8704 + 8704 + 4352 + 4352 + 512 + 64*3 + 8 + 256)

__global__ __launch_bounds__(256) void att_kernel(
    const float* __restrict__ feat,
    const float* __restrict__ b1,
    const float* __restrict__ g1, const float* __restrict__ be1,
    const float* __restrict__ W2, const float* __restrict__ b2)
{
    extern __shared__ uint32_t smw[];
    uint32_t* sAh = smw;                 // 128 x 68 = 8704
    uint32_t* sAl = sAh + 8704;          // 8704
    uint32_t* sWh = sAl + 8704;          // 64 x 68 = 4352
    uint32_t* sWl = sWh + 4352;          // 4352
    float* sW2  = (float*)(sWl + 4352);  // 512
    float* sB1  = sW2 + 512;             // 64
    float* sG1  = sB1 + 64;              // 64
    float* sBe1 = sG1 + 64;              // 64
    float* sB2  = sBe1 + 64;             // 8
    float* sMu  = sB2 + 8;               // 128
    float* sIs  = sMu + 128;             // 128
    float* sH   = (float*)sAh;           // alias, stride 65 (8320 <= 8704)

    int t = threadIdx.x;
    int row0 = blockIdx.x * 128;
    int wid = t >> 5, lane = t & 31;
    int g = lane >> 2, t4 = lane & 3;

    {   // stage A: feat 128x128 -> bf16 hi/lo packed (4096 float4, 16/thread)
        const float4* gsrc = (const float4*)(feat + (size_t)row0 * 128);
        #pragma unroll
        for (int e = 0; e < 16; e++){
            int i4 = t + 256*e;
            int r = i4 >> 5, c4 = i4 & 31;
            float4 a = gsrc[i4];
            uint32_t h0, l0, h1, l1;
            split2(a.x, a.y, h0, l0);
            split2(a.z, a.w, h1, l1);
            int base = r*68 + 2*c4;
            sAh[base] = h0; sAh[base+1] = h1;
            sAl[base] = l0; sAl[base+1] = l1;
        }
    }
    {   // stage B: copy prepacked W1 hi/lo (1024 uint4 each, 4/thread)
        #pragma unroll
        for (int e = 0; e < 4; e++){
            int i4 = t + 256*e;
            int n = i4 >> 4, c4 = i4 & 15;
            *(uint4*)&sWh[n*68 + 4*c4] = *(const uint4*)&g_W1h[n*64 + 4*c4];
            *(uint4*)&sWl[n*68 + 4*c4] = *(const uint4*)&g_W1l[n*64 + 4*c4];
        }
    }
    if (t < 128) ((float4*)sW2)[t] = ((const float4*)W2)[t];
    if (t < 64){ sB1[t] = b1[t]; sG1[t] = g1[t]; sBe1[t] = be1[t]; }
    if (t < 8)  sB2[t] = b2[t];
    __syncthreads();

    // GEMM1: warp = rows [wid*16, +16) x all 64 cols. K=128 -> 8 k16-steps.
    int rbase = wid * 16;
    float acc[8][4];
    #pragma unroll
    for (int j = 0; j < 8; j++){ acc[j][0]=acc[j][1]=acc[j][2]=acc[j][3]=0.f; }

    const uint32_t* Ah = sAh + (rbase + g) * 68;
    const uint32_t* Al = sAl + (rbase + g) * 68;

    #pragma unroll 2
    for (int ks = 0; ks < 8; ks++){
        int kw = ks*8 + t4;
        uint32_t ah0 = Ah[kw],     ah1 = Ah[kw + 8*68];
        uint32_t ah2 = Ah[kw + 4], ah3 = Ah[kw + 4 + 8*68];
        uint32_t al0 = Al[kw],     al1 = Al[kw + 8*68];
        uint32_t al2 = Al[kw + 4], al3 = Al[kw + 4 + 8*68];
        #pragma unroll
        for (int j = 0; j < 8; j++){
            const uint32_t* Bh = sWh + (j*8 + g)*68 + ks*8;
            const uint32_t* Bl = sWl + (j*8 + g)*68 + ks*8;
            uint32_t bh0 = Bh[t4], bh1 = Bh[t4 + 4];
            uint32_t bl0 = Bl[t4], bl1 = Bl[t4 + 4];
            mma_bf16(acc[j], ah0,ah1,ah2,ah3, bh0,bh1);
            mma_bf16(acc[j], al0,al1,al2,al3, bh0,bh1);
            mma_bf16(acc[j], ah0,ah1,ah2,ah3, bl0,bl1);
        }
    }
    __syncthreads();   // all sAh/sAl reads done before aliasing sAh as sH

    {   // epilogue: bias + leaky -> sH (stride 65); c-frag: rows g/g+8, cols 2t4/2t4+1
        int rA = rbase + g, rB = rA + 8;
        #pragma unroll
        for (int j = 0; j < 8; j++){
            int c = j*8 + 2*t4;
            sH[rA*65 + c]     = leaky(acc[j][0] + sB1[c]);
            sH[rA*65 + c + 1] = leaky(acc[j][1] + sB1[c+1]);
            sH[rB*65 + c]     = leaky(acc[j][2] + sB1[c]);
            sH[rB*65 + c + 1] = leaky(acc[j][3] + sB1[c+1]);
        }
    }
    __syncthreads();

    if (t < 128){   // LN stats per row
        float sum = 0.f, ss = 0.f;
        #pragma unroll 8
        for (int j = 0; j < 64; j++){ float v = sH[t*65 + j]; sum += v; ss += v*v; }
        float mu = sum * (1.f/64.f);
        float var = ss * (1.f/64.f) - mu*mu;
        sMu[t] = mu; sIs[t] = rsqrtf(var + EPS);
    }
    __syncthreads();

    {   // GEMM2 (64->8) + exp, 2 threads per row x 4 outputs (fp32, exact)
        int row = t >> 1, half = t & 1, kb = half * 4;
        float mu = sMu[row], is = sIs[row];
        float a0=0.f, a1=0.f, a2=0.f, a3=0.f;
        #pragma unroll 4
        for (int j = 0; j < 64; j++){
            float hn = (sH[row*65 + j] - mu) * is * sG1[j] + sBe1[j];
            a0 += hn * sW2[j*8 + kb + 0];
            a1 += hn * sW2[j*8 + kb + 1];
            a2 += hn * sW2[j*8 + kb + 2];
            a3 += hn * sW2[j*8 + kb + 3];
        }
        int grow = row0 + row;
        float4 o;
        o.x = __expf(a0 + sB2[kb+0]);
        o.y = __expf(a1 + sB2[kb+1]);
        o.z = __expf(a2 + sB2[kb+2]);
        o.w = __expf(a3 + sB2[kb+3]);
        *(float4*)&g_att[grow*8 + kb] = o;
    }
}

// ---------------- Pass B: single-pass segment softmax + aggregation ----------------
// R6-measured structure; bounds precomputed (removes per-block serial binary search).
__global__ __launch_bounds__(256) void aggregate_kernel(const float* __restrict__ feat){
    int gi = blockIdx.x;
    __shared__ __align__(16) float sF[32][128];
    __shared__ __align__(16) float sAtt[32][8];

    int t = threadIdx.x;
    int lo = g_seglo[gi], hi = g_seglo[gi + 1];
    int h = t >> 5, lane = t & 31;

    float4 acc = make_float4(0.f, 0.f, 0.f, 0.f);
    float ssum = 0.f;

    for (int base = lo; base < hi; base += 32){
        int cnt = min(32, hi - base);
        __syncthreads();
        for (int idx4 = t; idx4 < cnt*32; idx4 += 256){
            int r = idx4 >> 5, c4 = idx4 & 31;
            *(float4*)&sF[r][4*c4] = *(const float4*)&feat[(size_t)(base + r) * 128 + 4*c4];
        }
        if (t < cnt*8){
            int r = t >> 3, k = t & 7;
            sAtt[r][k] = g_att[(base + r)*8 + k];
        }
        __syncthreads();
        for (int r = 0; r < cnt; r++){
            float a = sAtt[r][h];
            ssum += a;
            float4 f = *(const float4*)&sF[r][lane*4];
            acc.x += a*f.x; acc.y += a*f.y; acc.z += a*f.z; acc.w += a*f.w;
        }
    }
    float inv = (hi > lo) ? 1.f / ssum : 0.f;
    acc.x *= inv; acc.y *= inv; acc.z *= inv; acc.w *= inv;
    *(float4*)&g_outflat[gi*1024 + h*128 + lane*4] = acc;
}

// ---------------- Pass C: GEMM3(bf16)+leaky+LN, GEMM4(bf16)+leaky+LN ----------------
// 16 graphs / block, 256 blocks, 256 threads. Warp w owns n-cols [w*16, +16) (jj 0..1).
#define FIN_SMEM_WORDS (8704 + 8704 + 1088 + 1088 + 2112 + 128*6 + 32)

__global__ __launch_bounds__(256) void final_kernel(
    const float* __restrict__ b3,
    const float* __restrict__ g3, const float* __restrict__ be3,
    const float* __restrict__ b4,
    const float* __restrict__ g4, const float* __restrict__ be4,
    float* __restrict__ out)
{
    extern __shared__ uint32_t smw[];
    uint32_t* sWh = smw;                 // 128 x 68 = 8704
    uint32_t* sWl = sWh + 8704;          // 8704
    uint32_t* sAh = sWl + 8704;          // 16 x 68 = 1088
    uint32_t* sAl = sAh + 1088;          // 1088
    float* sO1 = (float*)(sAl + 1088);   // 16 x 132 = 2112 (fp32 scratch)
    float* sB3 = sO1 + 2112;
    float* sG3 = sB3 + 128;
    float* sBe3= sG3 + 128;
    float* sB4 = sBe3+ 128;
    float* sG4 = sB4 + 128;
    float* sBe4= sG4 + 128;
    float* sMu = sBe4+ 128;              // 16
    float* sIs = sMu + 16;               // 16

    int t = threadIdx.x;
    int g0 = blockIdx.x * 16;
    int wid = t >> 5, lane = t & 31;
    int g = lane >> 2, t4 = lane & 3;

    if (t < 128){
        sB3[t]=b3[t]; sG3[t]=g3[t]; sBe3[t]=be3[t];
        sB4[t]=b4[t]; sG4[t]=g4[t]; sBe4[t]=be4[t];
    }

    // ---- GEMM3: [16,1024] @ [1024,128], 8 k-tiles of 128 (8 k16-steps each) ----
    float acc[2][4];
    acc[0][0]=acc[0][1]=acc[0][2]=acc[0][3]=0.f;
    acc[1][0]=acc[1][1]=acc[1][2]=acc[1][3]=0.f;

    for (int kt = 0; kt < 8; kt++){
        __syncthreads();
        {   // stage A slice 16x128 -> bf16 hi/lo (512 float4, 2/thread)
            #pragma unroll
            for (int e = 0; e < 2; e++){
                int i4 = t + 256*e;
                int r = i4 >> 5, c4 = i4 & 31;
                float4 a = *(const float4*)&g_outflat[(size_t)(g0 + r)*1024 + kt*128 + 4*c4];
                uint32_t h0, l0, h1, l1;
                split2(a.x, a.y, h0, l0);
                split2(a.z, a.w, h1, l1);
                int base = r*68 + 2*c4;
                sAh[base] = h0; sAh[base+1] = h1;
                sAl[base] = l0; sAl[base+1] = l1;
            }
        }
        {   // stage W3 hi/lo k-tile (2048 uint4 each, 8/thread)
            #pragma unroll
            for (int e = 0; e < 8; e++){
                int i4 = t + 256*e;
                int n = i4 >> 4, c4 = i4 & 15;
                *(uint4*)&sWh[n*68 + 4*c4] = *(const uint4*)&g_W3h[n*512 + kt*64 + 4*c4];
                *(uint4*)&sWl[n*68 + 4*c4] = *(const uint4*)&g_W3l[n*512 + kt*64 + 4*c4];
            }
        }
        __syncthreads();

        #pragma unroll 2
        for (int ks = 0; ks < 8; ks++){
            int kw = ks*8 + t4;
            uint32_t ah0 = sAh[g*68 + kw],     ah1 = sAh[(g+8)*68 + kw];
            uint32_t ah2 = sAh[g*68 + kw + 4], ah3 = sAh[(g+8)*68 + kw + 4];
            uint32_t al0 = sAl[g*68 + kw],     al1 = sAl[(g+8)*68 + kw];
            uint32_t al2 = sAl[g*68 + kw + 4], al3 = sAl[(g+8)*68 + kw + 4];
            #pragma unroll
            for (int jj = 0; jj < 2; jj++){
                const uint32_t* Bh = sWh + (wid*16 + jj*8 + g)*68 + ks*8;
                const uint32_t* Bl = sWl + (wid*16 + jj*8 + g)*68 + ks*8;
                uint32_t bh0 = Bh[t4], bh1 = Bh[t4 + 4];
                uint32_t bl0 = Bl[t4], bl1 = Bl[t4 + 4];
                mma_bf16(acc[jj], ah0,ah1,ah2,ah3, bh0,bh1);
                mma_bf16(acc[jj], al0,al1,al2,al3, bh0,bh1);
                mma_bf16(acc[jj], ah0,ah1,ah2,ah3, bl0,bl1);
            }
        }
    }
    __syncthreads();

    {   // epilogue GEMM3 -> sO1 (fp32); stage W4 hi/lo into sWh/sWl (W3 reads done)
        #pragma unroll
        for (int jj = 0; jj < 2; jj++){
            int c = wid*16 + jj*8 + 2*t4;
            sO1[g*132 + c]       = leaky(acc[jj][0] + sB3[c]);
            sO1[g*132 + c + 1]   = leaky(acc[jj][1] + sB3[c+1]);
            sO1[(g+8)*132 + c]   = leaky(acc[jj][2] + sB3[c]);
            sO1[(g+8)*132 + c+1] = leaky(acc[jj][3] + sB3[c+1]);
        }
        #pragma unroll
        for (int e = 0; e < 8; e++){
            int i4 = t + 256*e;
            int n = i4 >> 4, c4 = i4 & 15;
            *(uint4*)&sWh[n*68 + 4*c4] = *(const uint4*)&g_W4h[n*64 + 4*c4];
            *(uint4*)&sWl[n*68 + 4*c4] = *(const uint4*)&g_W4l[n*64 + 4*c4];
        }
    }
    __syncthreads();

    if (t < 16){   // LN1 stats
        float sum = 0.f, ss = 0.f;
        #pragma unroll 8
        for (int j = 0; j < 128; j++){ float v = sO1[t*132 + j]; sum += v; ss += v*v; }
        float mu = sum * (1.f/128.f);
        float var = ss * (1.f/128.f) - mu*mu;
        sMu[t] = mu; sIs[t] = rsqrtf(var + EPS);
    }
    __syncthreads();
    {   // LN1 apply + bf16 split into sAh/sAl (1024 words, 4/thread)
        #pragma unroll
        for (int e = 0; e < 4; e++){
            int w = t + 256*e;
            int r = w >> 6, kw = w & 63;
            int c = 2*kw;
            float mu = sMu[r], is = sIs[r];
            float v0 = (sO1[r*132 + c]     - mu) * is * sG3[c]   + sBe3[c];
            float v1 = (sO1[r*132 + c + 1] - mu) * is * sG3[c+1] + sBe3[c+1];
            uint32_t h, l;
            split2(v0, v1, h, l);
            sAh[r*68 + kw] = h;
            sAl[r*68 + kw] = l;
        }
    }
    __syncthreads();

    // ---- GEMM4: [16,128] @ [128,128] (8 k16-steps) ----
    float acc2[2][4];
    acc2[0][0]=acc2[0][1]=acc2[0][2]=acc2[0][3]=0.f;
    acc2[1][0]=acc2[1][1]=acc2[1][2]=acc2[1][3]=0.f;

    #pragma unroll 2
    for (int ks = 0; ks < 8; ks++){
        int kw = ks*8 + t4;
        uint32_t ah0 = sAh[g*68 + kw],     ah1 = sAh[(g+8)*68 + kw];
        uint32_t ah2 = sAh[g*68 + kw + 4], ah3 = sAh[(g+8)*68 + kw + 4];
        uint32_t al0 = sAl[g*68 + kw],     al1 = sAl[(g+8)*68 + kw];
        uint32_t al2 = sAl[g*68 + kw + 4], al3 = sAl[(g+8)*68 + kw + 4];
        #pragma unroll
        for (int jj = 0; jj < 2; jj++){
            const uint32_t* Bh = sWh + (wid*16 + jj*8 + g)*68 + ks*8;
            const uint32_t* Bl = sWl + (wid*16 + jj*8 + g)*68 + ks*8;
            uint32_t bh0 = Bh[t4], bh1 = Bh[t4 + 4];
            uint32_t bl0 = Bl[t4], bl1 = Bl[t4 + 4];
            mma_bf16(acc2[jj], ah0,ah1,ah2,ah3, bh0,bh1);
            mma_bf16(acc2[jj], al0,al1,al2,al3, bh0,bh1);
            mma_bf16(acc2[jj], ah0,ah1,ah2,ah3, bl0,bl1);
        }
    }
    __syncthreads();

    // epilogue GEMM4 -> sO1 (reuse as sO2)
    #pragma unroll
    for (int jj = 0; jj < 2; jj++){
        int c = wid*16 + jj*8 + 2*t4;
        sO1[g*132 + c]       = leaky(acc2[jj][0] + sB4[c]);
        sO1[g*132 + c + 1]   = leaky(acc2[jj][1] + sB4[c+1]);
        sO1[(g+8)*132 + c]   = leaky(acc2[jj][2] + sB4[c]);
        sO1[(g+8)*132 + c+1] = leaky(acc2[jj][3] + sB4[c+1]);
    }
    __syncthreads();

    if (t < 16){   // LN2 stats
        float sum = 0.f, ss = 0.f;
        #pragma unroll 8
        for (int j = 0; j < 128; j++){ float v = sO1[t*132 + j]; sum += v; ss += v*v; }
        float mu = sum * (1.f/128.f);
        float var = ss * (1.f/128.f) - mu*mu;
        sMu[t] = mu; sIs[t] = rsqrtf(var + EPS);
    }
    __syncthreads();
    #pragma unroll
    for (int e = 0; e < 8; e++){
        int idx = t + 256*e;
        int r = idx >> 7, c = idx & 127;
        out[(g0 + r)*128 + c] = (sO1[r*132 + c] - sMu[r]) * sIs[r] * sG4[c] + sBe4[c];
    }
}

// ---------------- host ----------------
extern "C" void kernel_launch(void* const* d_in, const int* in_sizes, int n_in,
                              void* d_out, int out_size)
{
    const float* feat = (const float*)d_in[0];
    const int*   batch = (const int*)d_in[1];
    const float* W1 = (const float*)d_in[2];
    const float* b1 = (const float*)d_in[3];
    const float* g1 = (const float*)d_in[4];
    const float* be1= (const float*)d_in[5];
    const float* W2 = (const float*)d_in[6];
    const float* b2 = (const float*)d_in[7];
    const float* W3 = (const float*)d_in[8];
    const float* b3 = (const float*)d_in[9];
    const float* g3 = (const float*)d_in[10];
    const float* be3= (const float*)d_in[11];
    const float* W4 = (const float*)d_in[12];
    const float* b4 = (const float*)d_in[13];
    const float* g4 = (const float*)d_in[14];
    const float* be4= (const float*)d_in[15];

    int nrows = in_sizes[0] / 128;

    const int att_smem = ATT_SMEM_WORDS * 4;   // 108,320 B -> 2 CTAs/SM
    const int fin_smem = FIN_SMEM_WORDS * 4;   //  89,984 B -> 2 CTAs/SM
    cudaFuncSetAttribute(att_kernel,   cudaFuncAttributeMaxDynamicSharedMemorySize, att_smem);
    cudaFuncSetAttribute(final_kernel, cudaFuncAttributeMaxDynamicSharedMemorySize, fin_smem);

    detect_kernel<<<1, 256>>>(batch, nrows);
    bounds_kernel<<<NGRAPH / 256, 256>>>(batch, nrows);
    prep_kernel<<<304, 256>>>(W1, W3, W4);
    att_kernel<<<nrows / 128, 256, att_smem>>>(feat, b1, g1, be1, W2, b2);
    aggregate_kernel<<<NGRAPH, 256>>>(feat);
    final_kernel<<<NGRAPH / 16, 256, fin_smem>>>(b3, g3, be3, b4, g4, be4, (float*)d_out);
}

// round 12
// speedup vs baseline: 1.4910x; 1.0227x over previous
#include <cuda_runtime.h>
#include <cuda_bf16.h>
#include <cstdint>

#define NGRAPH 4096
#define EPS 1e-6f

// ---------------- device scratch ----------------
__device__ __align__(16) float g_att[262144 * 8];          // exp attention, unnormalized [N,8]
__device__ __align__(16) float g_outflat[NGRAPH * 1024];   // aggregated [B, H*D]
__device__ __align__(16) unsigned int g_W1h[64 * 64];      // W1 packed bf16x2 [n][kw]
__device__ __align__(16) unsigned int g_W1l[64 * 64];
__device__ __align__(16) unsigned int g_W3h[128 * 512];    // W3 packed [n][kw]
__device__ __align__(16) unsigned int g_W3l[128 * 512];
__device__ __align__(16) unsigned int g_W4h[128 * 64];     // W4 packed [n][kw]
__device__ __align__(16) unsigned int g_W4l[128 * 64];
__device__ int g_seglo[NGRAPH + 1];
__device__ int g_is64;

__device__ __forceinline__ float leaky(float x){ return x > 0.f ? x : 0.01f * x; }

// split (x,y) into bf16 hi/lo pairs packed as bf16x2 words (x in LOW half).
__device__ __forceinline__ void split2(float x, float y, uint32_t& h, uint32_t& l){
    __nv_bfloat16 hx = __float2bfloat16_rn(x);
    __nv_bfloat16 hy = __float2bfloat16_rn(y);
    float rx = x - __bfloat162float(hx);
    float ry = y - __bfloat162float(hy);
    __nv_bfloat162 hh = __halves2bfloat162(hx, hy);           // .x = low half
    __nv_bfloat162 ll = __halves2bfloat162(__float2bfloat16_rn(rx), __float2bfloat16_rn(ry));
    h = *reinterpret_cast<uint32_t*>(&hh);
    l = *reinterpret_cast<uint32_t*>(&ll);
}

// D += A(16x16 bf16) * B(16x8 bf16), fp32 accumulate
__device__ __forceinline__ void mma_bf16(float* c,
    uint32_t a0, uint32_t a1, uint32_t a2, uint32_t a3, uint32_t b0, uint32_t b1){
    asm volatile(
      "mma.sync.aligned.m16n8k16.row.col.f32.bf16.bf16.f32 "
      "{%0,%1,%2,%3}, {%4,%5,%6,%7}, {%8,%9}, {%0,%1,%2,%3};\n"
      : "+f"(c[0]), "+f"(c[1]), "+f"(c[2]), "+f"(c[3])
      : "r"(a0), "r"(a1), "r"(a2), "r"(a3), "r"(b0), "r"(b1));
}

// ldmatrix x4 (non-transposed, b16)
__device__ __forceinline__ void ldsm_x4(uint32_t& r0, uint32_t& r1, uint32_t& r2, uint32_t& r3,
                                        uint32_t addr){
    asm volatile("ldmatrix.sync.aligned.m8n8.x4.shared.b16 {%0,%1,%2,%3}, [%4];"
        : "=r"(r0), "=r"(r1), "=r"(r2), "=r"(r3) : "r"(addr));
}

// Parallel batch dtype detection (int32 loads only).
__global__ void detect_kernel(const int* __restrict__ batch, int n){
    __shared__ int bad;
    if (threadIdx.x == 0) bad = 0;
    __syncthreads();
    int base = n / 2;
    int i = threadIdx.x;
    int lo = batch[base + 2*i];
    int hi = batch[base + 2*i + 1];
    if (hi != 0 || lo < 0 || lo >= NGRAPH) bad = 1;
    __syncthreads();
    if (threadIdx.x == 0) g_is64 = (bad == 0);
}

__device__ __forceinline__ int bat(const int* b, int i, int is64){
    return is64 ? b[2*i] : b[i];
}

__device__ __forceinline__ int lbound(const int* b, int n, int val, int is64){
    int lo = 0, hi = n;
    while (lo < hi){
        int mid = (lo + hi) >> 1;
        if (bat(b, mid, is64) < val) lo = mid + 1; else hi = mid;
    }
    return lo;
}

// ---------------- segment bounds: one thread per graph ----------------
__global__ void bounds_kernel(const int* __restrict__ batch, int n){
    int g = blockIdx.x * 256 + threadIdx.x;
    int is64 = g_is64;
    if (g < NGRAPH) g_seglo[g] = lbound(batch, n, g, is64);
    if (g == 0)     g_seglo[NGRAPH] = n;
}

// ---------------- weight prep: pack W1/W3/W4 as bf16x2 hi/lo, [n][kword] ----------------
__global__ void prep_kernel(const float* __restrict__ W1,
                            const float* __restrict__ W3,
                            const float* __restrict__ W4){
    int idx = blockIdx.x * 256 + threadIdx.x;
    if (idx < 4096){                               // W1: [128 k][64 n] -> [64 n][64 kw]
        int n = idx >> 6, kw = idx & 63;
        uint32_t h, l;
        split2(W1[(2*kw)*64 + n], W1[(2*kw+1)*64 + n], h, l);
        g_W1h[idx] = h; g_W1l[idx] = l;
        return;
    }
    int j = idx - 4096;
    if (j < 65536){                                // W3: [1024 k][128 n] -> [128 n][512 kw]
        int n = j >> 9, kw = j & 511;
        uint32_t h, l;
        split2(W3[(2*kw)*128 + n], W3[(2*kw+1)*128 + n], h, l);
        g_W3h[j] = h; g_W3l[j] = l;
        return;
    }
    int m = j - 65536;
    if (m < 8192){                                 // W4: [128 k][128 n] -> [128 n][64 kw]
        int n = m >> 6, kw = m & 63;
        uint32_t h, l;
        split2(W4[(2*kw)*128 + n], W4[(2*kw+1)*128 + n], h, l);
        g_W4h[m] = h; g_W4l[m] = l;
    }
}

// ---------------- Pass A: GEMM1 (bf16 split mma, ldmatrix) + leaky + LN + GEMM2 + exp ----------------
// 128 rows / block, 256 threads (8 warps, one 16-row M-tile each, full 64 cols), 2048 blocks.
#define ATT_SMEM_WORDS (8704 + 8704 + 4352 + 4352 + 512 + 64*3 + 8 + 256)

__global__ __launch_bounds__(256) void att_kernel(
    const float* __restrict__ feat,
    const float* __restrict__ b1,
    const float* __restrict__ g1, const float* __restrict__ be1,
    const float* __restrict__ W2, const float* __restrict__ b2)
{
    extern __shared__ uint32_t smw[];
    uint32_t* sAh = smw;                 // 128 x 68 = 8704
    uint32_t* sAl = sAh + 8704;          // 8704
    uint32_t* sWh = sAl + 8704;          // 64 x 68 = 4352
    uint32_t* sWl = sWh + 4352;          // 4352
    float* sW2  = (float*)(sWl + 4352);  // 512
    float* sB1  = sW2 + 512;             // 64
    float* sG1  = sB1 + 64;              // 64
    float* sBe1 = sG1 + 64;              // 64
    float* sB2  = sBe1 + 64;             // 8
    float* sMu  = sB2 + 8;               // 128
    float* sIs  = sMu + 128;             // 128
    float* sH   = (float*)sAh;           // alias, stride 65 (8320 <= 8704)

    int t = threadIdx.x;
    int row0 = blockIdx.x * 128;
    int wid = t >> 5, lane = t & 31;
    int g = lane >> 2, t4 = lane & 3;

    {   // stage A: feat 128x128 -> bf16 hi/lo packed (4096 float4, 16/thread)
        const float4* gsrc = (const float4*)(feat + (size_t)row0 * 128);
        #pragma unroll
        for (int e = 0; e < 16; e++){
            int i4 = t + 256*e;
            int r = i4 >> 5, c4 = i4 & 31;
            float4 a = gsrc[i4];
            uint32_t h0, l0, h1, l1;
            split2(a.x, a.y, h0, l0);
            split2(a.z, a.w, h1, l1);
            int base = r*68 + 2*c4;
            sAh[base] = h0; sAh[base+1] = h1;
            sAl[base] = l0; sAl[base+1] = l1;
        }
    }
    {   // stage B: copy prepacked W1 hi/lo
        #pragma unroll
        for (int e = 0; e < 4; e++){
            int i4 = t + 256*e;
            int n = i4 >> 4, c4 = i4 & 15;
            *(uint4*)&sWh[n*68 + 4*c4] = *(const uint4*)&g_W1h[n*64 + 4*c4];
            *(uint4*)&sWl[n*68 + 4*c4] = *(const uint4*)&g_W1l[n*64 + 4*c4];
        }
    }
    if (t < 128) ((float4*)sW2)[t] = ((const float4*)W2)[t];
    if (t < 64){ sB1[t] = b1[t]; sG1[t] = g1[t]; sBe1[t] = be1[t]; }
    if (t < 8)  sB2[t] = b2[t];
    __syncthreads();

    // GEMM1: warp = rows [wid*16, +16) x all 64 cols. K=128 -> 8 k16-steps.
    int rbase = wid * 16;
    float acc[8][4];
    #pragma unroll
    for (int j = 0; j < 8; j++){ acc[j][0]=acc[j][1]=acc[j][2]=acc[j][3]=0.f; }

    // ldmatrix fragment base addresses
    uint32_t aBaseH, aBaseL;
    {
        int rowf = rbase + (lane & 7) + ((lane >> 3) & 1) * 8;
        int kws  = ((lane >> 4) & 1) * 4;
        aBaseH = (uint32_t)__cvta_generic_to_shared(sAh + rowf*68 + kws);
        aBaseL = (uint32_t)__cvta_generic_to_shared(sAl + rowf*68 + kws);
    }
    uint32_t bBaseH[4], bBaseL[4];
    #pragma unroll
    for (int jp = 0; jp < 4; jp++){
        int nf  = (2*jp + ((lane >> 4) & 1)) * 8 + (lane & 7);
        int kws = ((lane >> 3) & 1) * 4;
        bBaseH[jp] = (uint32_t)__cvta_generic_to_shared(sWh + nf*68 + kws);
        bBaseL[jp] = (uint32_t)__cvta_generic_to_shared(sWl + nf*68 + kws);
    }

    #pragma unroll 2
    for (int ks = 0; ks < 8; ks++){
        uint32_t off = (uint32_t)ks * 32;   // 8 words per k16-step
        uint32_t ah0,ah1,ah2,ah3, al0,al1,al2,al3;
        ldsm_x4(ah0,ah1,ah2,ah3, aBaseH + off);
        ldsm_x4(al0,al1,al2,al3, aBaseL + off);
        #pragma unroll
        for (int jp = 0; jp < 4; jp++){
            uint32_t bh0,bh1,bh2,bh3, bl0,bl1,bl2,bl3;
            ldsm_x4(bh0,bh1,bh2,bh3, bBaseH[jp] + off);
            ldsm_x4(bl0,bl1,bl2,bl3, bBaseL[jp] + off);
            mma_bf16(acc[2*jp],   ah0,ah1,ah2,ah3, bh0,bh1);
            mma_bf16(acc[2*jp],   al0,al1,al2,al3, bh0,bh1);
            mma_bf16(acc[2*jp],   ah0,ah1,ah2,ah3, bl0,bl1);
            mma_bf16(acc[2*jp+1], ah0,ah1,ah2,ah3, bh2,bh3);
            mma_bf16(acc[2*jp+1], al0,al1,al2,al3, bh2,bh3);
            mma_bf16(acc[2*jp+1], ah0,ah1,ah2,ah3, bl2,bl3);
        }
    }
    __syncthreads();   // all sAh/sAl reads done before aliasing sAh as sH

    {   // epilogue: bias + leaky -> sH (stride 65)
        int rA = rbase + g, rB = rA + 8;
        #pragma unroll
        for (int j = 0; j < 8; j++){
            int c = j*8 + 2*t4;
            sH[rA*65 + c]     = leaky(acc[j][0] + sB1[c]);
            sH[rA*65 + c + 1] = leaky(acc[j][1] + sB1[c+1]);
            sH[rB*65 + c]     = leaky(acc[j][2] + sB1[c]);
            sH[rB*65 + c + 1] = leaky(acc[j][3] + sB1[c+1]);
        }
    }
    __syncthreads();

    if (t < 128){   // LN stats per row
        float sum = 0.f, ss = 0.f;
        #pragma unroll 8
        for (int j = 0; j < 64; j++){ float v = sH[t*65 + j]; sum += v; ss += v*v; }
        float mu = sum * (1.f/64.f);
        float var = ss * (1.f/64.f) - mu*mu;
        sMu[t] = mu; sIs[t] = rsqrtf(var + EPS);
    }
    __syncthreads();

    {   // GEMM2 (64->8) + exp (fp32, exact)
        int row = t >> 1, half = t & 1, kb = half * 4;
        float mu = sMu[row], is = sIs[row];
        float a0=0.f, a1=0.f, a2=0.f, a3=0.f;
        #pragma unroll 4
        for (int j = 0; j < 64; j++){
            float hn = (sH[row*65 + j] - mu) * is * sG1[j] + sBe1[j];
            a0 += hn * sW2[j*8 + kb + 0];
            a1 += hn * sW2[j*8 + kb + 1];
            a2 += hn * sW2[j*8 + kb + 2];
            a3 += hn * sW2[j*8 + kb + 3];
        }
        int grow = row0 + row;
        float4 o;
        o.x = __expf(a0 + sB2[kb+0]);
        o.y = __expf(a1 + sB2[kb+1]);
        o.z = __expf(a2 + sB2[kb+2]);
        o.w = __expf(a3 + sB2[kb+3]);
        *(float4*)&g_att[grow*8 + kb] = o;
    }
}

// ---------------- Pass B: single-pass segment softmax + aggregation ----------------
__global__ __launch_bounds__(256) void aggregate_kernel(const float* __restrict__ feat){
    int gi = blockIdx.x;
    __shared__ __align__(16) float sF[32][128];
    __shared__ __align__(16) float sAtt[32][8];

    int t = threadIdx.x;
    int lo = g_seglo[gi], hi = g_seglo[gi + 1];
    int h = t >> 5, lane = t & 31;

    float4 acc = make_float4(0.f, 0.f, 0.f, 0.f);
    float ssum = 0.f;

    for (int base = lo; base < hi; base += 32){
        int cnt = min(32, hi - base);
        __syncthreads();
        for (int idx4 = t; idx4 < cnt*32; idx4 += 256){
            int r = idx4 >> 5, c4 = idx4 & 31;
            *(float4*)&sF[r][4*c4] = *(const float4*)&feat[(size_t)(base + r) * 128 + 4*c4];
        }
        if (t < cnt*8){
            int r = t >> 3, k = t & 7;
            sAtt[r][k] = g_att[(base + r)*8 + k];
        }
        __syncthreads();
        for (int r = 0; r < cnt; r++){
            float a = sAtt[r][h];
            ssum += a;
            float4 f = *(const float4*)&sF[r][lane*4];
            acc.x += a*f.x; acc.y += a*f.y; acc.z += a*f.z; acc.w += a*f.w;
        }
    }
    float inv = (hi > lo) ? 1.f / ssum : 0.f;
    acc.x *= inv; acc.y *= inv; acc.z *= inv; acc.w *= inv;
    *(float4*)&g_outflat[gi*1024 + h*128 + lane*4] = acc;
}

// ---------------- Pass C: GEMM3(bf16,ldmatrix)+leaky+LN, GEMM4(bf16,ldmatrix)+leaky+LN ----------------
// 16 graphs / block, 256 blocks, 256 threads. Warp w owns n-cols [w*16, +16).
#define FIN_SMEM_WORDS (8704 + 8704 + 1088 + 1088 + 2112 + 128*6 + 32)

__global__ __launch_bounds__(256) void final_kernel(
    const float* __restrict__ b3,
    const float* __restrict__ g3, const float* __restrict__ be3,
    const float* __restrict__ b4,
    const float* __restrict__ g4, const float* __restrict__ be4,
    float* __restrict__ out)
{
    extern __shared__ uint32_t smw[];
    uint32_t* sWh = smw;                 // 128 x 68 = 8704
    uint32_t* sWl = sWh + 8704;          // 8704
    uint32_t* sAh = sWl + 8704;          // 16 x 68 = 1088
    uint32_t* sAl = sAh + 1088;          // 1088
    float* sO1 = (float*)(sAl + 1088);   // 16 x 132 = 2112 (fp32 scratch)
    float* sB3 = sO1 + 2112;
    float* sG3 = sB3 + 128;
    float* sBe3= sG3 + 128;
    float* sB4 = sBe3+ 128;
    float* sG4 = sB4 + 128;
    float* sBe4= sG4 + 128;
    float* sMu = sBe4+ 128;              // 16
    float* sIs = sMu + 16;               // 16

    int t = threadIdx.x;
    int g0 = blockIdx.x * 16;
    int wid = t >> 5, lane = t & 31;
    int g = lane >> 2, t4 = lane & 3;

    if (t < 128){
        sB3[t]=b3[t]; sG3[t]=g3[t]; sBe3[t]=be3[t];
        sB4[t]=b4[t]; sG4[t]=g4[t]; sBe4[t]=be4[t];
    }

    // ldmatrix fragment base addresses (A rows 0-15; B n-block = warp's 16 cols)
    uint32_t aBaseH, aBaseL, bBaseH, bBaseL;
    {
        int rowf = (lane & 7) + ((lane >> 3) & 1) * 8;
        int kwsA = ((lane >> 4) & 1) * 4;
        aBaseH = (uint32_t)__cvta_generic_to_shared(sAh + rowf*68 + kwsA);
        aBaseL = (uint32_t)__cvta_generic_to_shared(sAl + rowf*68 + kwsA);
        int nf   = wid*16 + ((lane >> 4) & 1) * 8 + (lane & 7);
        int kwsB = ((lane >> 3) & 1) * 4;
        bBaseH = (uint32_t)__cvta_generic_to_shared(sWh + nf*68 + kwsB);
        bBaseL = (uint32_t)__cvta_generic_to_shared(sWl + nf*68 + kwsB);
    }

    // ---- GEMM3: [16,1024] @ [1024,128], 8 k-tiles of 128 (8 k16-steps each) ----
    float acc[2][4];
    acc[0][0]=acc[0][1]=acc[0][2]=acc[0][3]=0.f;
    acc[1][0]=acc[1][1]=acc[1][2]=acc[1][3]=0.f;

    for (int kt = 0; kt < 8; kt++){
        __syncthreads();
        {   // stage A slice 16x128 -> bf16 hi/lo (512 float4, 2/thread)
            #pragma unroll
            for (int e = 0; e < 2; e++){
                int i4 = t + 256*e;
                int r = i4 >> 5, c4 = i4 & 31;
                float4 a = *(const float4*)&g_outflat[(size_t)(g0 + r)*1024 + kt*128 + 4*c4];
                uint32_t h0, l0, h1, l1;
                split2(a.x, a.y, h0, l0);
                split2(a.z, a.w, h1, l1);
                int base = r*68 + 2*c4;
                sAh[base] = h0; sAh[base+1] = h1;
                sAl[base] = l0; sAl[base+1] = l1;
            }
        }
        {   // stage W3 hi/lo k-tile
            #pragma unroll
            for (int e = 0; e < 8; e++){
                int i4 = t + 256*e;
                int n = i4 >> 4, c4 = i4 & 15;
                *(uint4*)&sWh[n*68 + 4*c4] = *(const uint4*)&g_W3h[n*512 + kt*64 + 4*c4];
                *(uint4*)&sWl[n*68 + 4*c4] = *(const uint4*)&g_W3l[n*512 + kt*64 + 4*c4];
            }
        }
        __syncthreads();

        #pragma unroll 2
        for (int ks = 0; ks < 8; ks++){
            uint32_t off = (uint32_t)ks * 32;
            uint32_t ah0,ah1,ah2,ah3, al0,al1,al2,al3;
            ldsm_x4(ah0,ah1,ah2,ah3, aBaseH + off);
            ldsm_x4(al0,al1,al2,al3, aBaseL + off);
            uint32_t bh0,bh1,bh2,bh3, bl0,bl1,bl2,bl3;
            ldsm_x4(bh0,bh1,bh2,bh3, bBaseH + off);
            ldsm_x4(bl0,bl1,bl2,bl3, bBaseL + off);
            mma_bf16(acc[0], ah0,ah1,ah2,ah3, bh0,bh1);
            mma_bf16(acc[0], al0,al1,al2,al3, bh0,bh1);
            mma_bf16(acc[0], ah0,ah1,ah2,ah3, bl0,bl1);
            mma_bf16(acc[1], ah0,ah1,ah2,ah3, bh2,bh3);
            mma_bf16(acc[1], al0,al1,al2,al3, bh2,bh3);
            mma_bf16(acc[1], ah0,ah1,ah2,ah3, bl2,bl3);
        }
    }
    __syncthreads();

    {   // epilogue GEMM3 -> sO1 (fp32); stage W4 hi/lo into sWh/sWl
        #pragma unroll
        for (int jj = 0; jj < 2; jj++){
            int c = wid*16 + jj*8 + 2*t4;
            sO1[g*132 + c]       = leaky(acc[jj][0] + sB3[c]);
            sO1[g*132 + c + 1]   = leaky(acc[jj][1] + sB3[c+1]);
            sO1[(g+8)*132 + c]   = leaky(acc[jj][2] + sB3[c]);
            sO1[(g+8)*132 + c+1] = leaky(acc[jj][3] + sB3[c+1]);
        }
        #pragma unroll
        for (int e = 0; e < 8; e++){
            int i4 = t + 256*e;
            int n = i4 >> 4, c4 = i4 & 15;
            *(uint4*)&sWh[n*68 + 4*c4] = *(const uint4*)&g_W4h[n*64 + 4*c4];
            *(uint4*)&sWl[n*68 + 4*c4] = *(const uint4*)&g_W4l[n*64 + 4*c4];
        }
    }
    __syncthreads();

    if (t < 16){   // LN1 stats
        float sum = 0.f, ss = 0.f;
        #pragma unroll 8
        for (int j = 0; j < 128; j++){ float v = sO1[t*132 + j]; sum += v; ss += v*v; }
        float mu = sum * (1.f/128.f);
        float var = ss * (1.f/128.f) - mu*mu;
        sMu[t] = mu; sIs[t] = rsqrtf(var + EPS);
    }
    __syncthreads();
    {   // LN1 apply + bf16 split into sAh/sAl (1024 words, 4/thread)
        #pragma unroll
        for (int e = 0; e < 4; e++){
            int w = t + 256*e;
            int r = w >> 6, kw = w & 63;
            int c = 2*kw;
            float mu = sMu[r], is = sIs[r];
            float v0 = (sO1[r*132 + c]     - mu) * is * sG3[c]   + sBe3[c];
            float v1 = (sO1[r*132 + c + 1] - mu) * is * sG3[c+1] + sBe3[c+1];
            uint32_t h, l;
            split2(v0, v1, h, l);
            sAh[r*68 + kw] = h;
            sAl[r*68 + kw] = l;
        }
    }
    __syncthreads();

    // ---- GEMM4: [16,128] @ [128,128] (8 k16-steps) ----
    float acc2[2][4];
    acc2[0][0]=acc2[0][1]=acc2[0][2]=acc2[0][3]=0.f;
    acc2[1][0]=acc2[1][1]=acc2[1][2]=acc2[1][3]=0.f;

    #pragma unroll 2
    for (int ks = 0; ks < 8; ks++){
        uint32_t off = (uint32_t)ks * 32;
        uint32_t ah0,ah1,ah2,ah3, al0,al1,al2,al3;
        ldsm_x4(ah0,ah1,ah2,ah3, aBaseH + off);
        ldsm_x4(al0,al1,al2,al3, aBaseL + off);
        uint32_t bh0,bh1,bh2,bh3, bl0,bl1,bl2,bl3;
        ldsm_x4(bh0,bh1,bh2,bh3, bBaseH + off);
        ldsm_x4(bl0,bl1,bl2,bl3, bBaseL + off);
        mma_bf16(acc2[0], ah0,ah1,ah2,ah3, bh0,bh1);
        mma_bf16(acc2[0], al0,al1,al2,al3, bh0,bh1);
        mma_bf16(acc2[0], ah0,ah1,ah2,ah3, bl0,bl1);
        mma_bf16(acc2[1], ah0,ah1,ah2,ah3, bh2,bh3);
        mma_bf16(acc2[1], al0,al1,al2,al3, bh2,bh3);
        mma_bf16(acc2[1], ah0,ah1,ah2,ah3, bl2,bl3);
    }
    __syncthreads();

    // epilogue GEMM4 -> sO1 (reuse as sO2)
    #pragma unroll
    for (int jj = 0; jj < 2; jj++){
        int c = wid*16 + jj*8 + 2*t4;
        sO1[g*132 + c]       = leaky(acc2[jj][0] + sB4[c]);
        sO1[g*132 + c + 1]   = leaky(acc2[jj][1] + sB4[c+1]);
        sO1[(g+8)*132 + c]   = leaky(acc2[jj][2] + sB4[c]);
        sO1[(g+8)*132 + c+1] = leaky(acc2[jj][3] + sB4[c+1]);
    }
    __syncthreads();

    if (t < 16){   // LN2 stats
        float sum = 0.f, ss = 0.f;
        #pragma unroll 8
        for (int j = 0; j < 128; j++){ float v = sO1[t*132 + j]; sum += v; ss += v*v; }
        float mu = sum * (1.f/128.f);
        float var = ss * (1.f/128.f) - mu*mu;
        sMu[t] = mu; sIs[t] = rsqrtf(var + EPS);
    }
    __syncthreads();
    #pragma unroll
    for (int e = 0; e < 8; e++){
        int idx = t + 256*e;
        int r = idx >> 7, c = idx & 127;
        out[(g0 + r)*128 + c] = (sO1[r*132 + c] - sMu[r]) * sIs[r] * sG4[c] + sBe4[c];
    }
}

// ---------------- host ----------------
extern "C" void kernel_launch(void* const* d_in, const int* in_sizes, int n_in,
                              void* d_out, int out_size)
{
    const float* feat = (const float*)d_in[0];
    const int*   batch = (const int*)d_in[1];
    const float* W1 = (const float*)d_in[2];
    const float* b1 = (const float*)d_in[3];
    const float* g1 = (const float*)d_in[4];
    const float* be1= (const float*)d_in[5];
    const float* W2 = (const float*)d_in[6];
    const float* b2 = (const float*)d_in[7];
    const float* W3 = (const float*)d_in[8];
    const float* b3 = (const float*)d_in[9];
    const float* g3 = (const float*)d_in[10];
    const float* be3= (const float*)d_in[11];
    const float* W4 = (const float*)d_in[12];
    const float* b4 = (const float*)d_in[13];
    const float* g4 = (const float*)d_in[14];
    const float* be4= (const float*)d_in[15];

    int nrows = in_sizes[0] / 128;

    const int att_smem = ATT_SMEM_WORDS * 4;   // 108,320 B -> 2 CTAs/SM
    const int fin_smem = FIN_SMEM_WORDS * 4;   //  89,984 B -> 2 CTAs/SM
    cudaFuncSetAttribute(att_kernel,   cudaFuncAttributeMaxDynamicSharedMemorySize, att_smem);
    cudaFuncSetAttribute(final_kernel, cudaFuncAttributeMaxDynamicSharedMemorySize, fin_smem);

    detect_kernel<<<1, 256>>>(batch, nrows);
    bounds_kernel<<<NGRAPH / 256, 256>>>(batch, nrows);
    prep_kernel<<<304, 256>>>(W1, W3, W4);
    att_kernel<<<nrows / 128, 256, att_smem>>>(feat, b1, g1, be1, W2, b2);
    aggregate_kernel<<<NGRAPH, 256>>>(feat);
    final_kernel<<<NGRAPH / 16, 256, fin_smem>>>(b3, g3, be3, b4, g4, be4, (float*)d_out);
}

// round 14
// speedup vs baseline: 1.5808x; 1.0602x over previous
#include <cuda_runtime.h>
#include <cuda_bf16.h>
#include <cstdint>

#define NGRAPH 4096
#define EPS 1e-6f

// ---------------- device scratch ----------------
__device__ __align__(16) float g_att[262144 * 8];          // exp attention, unnormalized [N,8]
__device__ __align__(16) float g_outflat[NGRAPH * 1024];   // aggregated [B, H*D]
__device__ __align__(16) unsigned int g_W1h[64 * 64];      // W1 packed bf16x2 [n][kw]
__device__ __align__(16) unsigned int g_W1l[64 * 64];
__device__ __align__(16) unsigned int g_W3h[128 * 512];    // W3 packed [n][kw]
__device__ __align__(16) unsigned int g_W3l[128 * 512];
__device__ __align__(16) unsigned int g_W4h[128 * 64];     // W4 packed [n][kw]
__device__ __align__(16) unsigned int g_W4l[128 * 64];
__device__ int g_seglo[NGRAPH + 1];
__device__ int g_is64;

__device__ __forceinline__ float leaky(float x){ return x > 0.f ? x : 0.01f * x; }

// split (x,y) into bf16 hi/lo pairs packed as bf16x2 words (x in LOW half).
__device__ __forceinline__ void split2(float x, float y, uint32_t& h, uint32_t& l){
    __nv_bfloat16 hx = __float2bfloat16_rn(x);
    __nv_bfloat16 hy = __float2bfloat16_rn(y);
    float rx = x - __bfloat162float(hx);
    float ry = y - __bfloat162float(hy);
    __nv_bfloat162 hh = __halves2bfloat162(hx, hy);           // .x = low half
    __nv_bfloat162 ll = __halves2bfloat162(__float2bfloat16_rn(rx), __float2bfloat16_rn(ry));
    h = *reinterpret_cast<uint32_t*>(&hh);
    l = *reinterpret_cast<uint32_t*>(&ll);
}

// D += A(16x16 bf16) * B(16x8 bf16), fp32 accumulate
__device__ __forceinline__ void mma_bf16(float* c,
    uint32_t a0, uint32_t a1, uint32_t a2, uint32_t a3, uint32_t b0, uint32_t b1){
    asm volatile(
      "mma.sync.aligned.m16n8k16.row.col.f32.bf16.bf16.f32 "
      "{%0,%1,%2,%3}, {%4,%5,%6,%7}, {%8,%9}, {%0,%1,%2,%3};\n"
      : "+f"(c[0]), "+f"(c[1]), "+f"(c[2]), "+f"(c[3])
      : "r"(a0), "r"(a1), "r"(a2), "r"(a3), "r"(b0), "r"(b1));
}

// ldmatrix x4 (non-transposed, b16)
__device__ __forceinline__ void ldsm_x4(uint32_t& r0, uint32_t& r1, uint32_t& r2, uint32_t& r3,
                                        uint32_t addr){
    asm volatile("ldmatrix.sync.aligned.m8n8.x4.shared.b16 {%0,%1,%2,%3}, [%4];"
        : "=r"(r0), "=r"(r1), "=r"(r2), "=r"(r3) : "r"(addr));
}

// Parallel batch dtype detection (int32 loads only).
__global__ void detect_kernel(const int* __restrict__ batch, int n){
    __shared__ int bad;
    if (threadIdx.x == 0) bad = 0;
    __syncthreads();
    int base = n / 2;
    int i = threadIdx.x;
    int lo = batch[base + 2*i];
    int hi = batch[base + 2*i + 1];
    if (hi != 0 || lo < 0 || lo >= NGRAPH) bad = 1;
    __syncthreads();
    if (threadIdx.x == 0) g_is64 = (bad == 0);
}

__device__ __forceinline__ int bat(const int* b, int i, int is64){
    return is64 ? b[2*i] : b[i];
}

__device__ __forceinline__ int lbound(const int* b, int n, int val, int is64){
    int lo = 0, hi = n;
    while (lo < hi){
        int mid = (lo + hi) >> 1;
        if (bat(b, mid, is64) < val) lo = mid + 1; else hi = mid;
    }
    return lo;
}

// ---------------- segment bounds: one thread per graph ----------------
__global__ void bounds_kernel(const int* __restrict__ batch, int n){
    int g = blockIdx.x * 256 + threadIdx.x;
    int is64 = g_is64;
    if (g < NGRAPH) g_seglo[g] = lbound(batch, n, g, is64);
    if (g == 0)     g_seglo[NGRAPH] = n;
}

// ---------------- weight prep: pack W1/W3/W4 as bf16x2 hi/lo, [n][kword] ----------------
__global__ void prep_kernel(const float* __restrict__ W1,
                            const float* __restrict__ W3,
                            const float* __restrict__ W4){
    int idx = blockIdx.x * 256 + threadIdx.x;
    if (idx < 4096){                               // W1: [128 k][64 n] -> [64 n][64 kw]
        int n = idx >> 6, kw = idx & 63;
        uint32_t h, l;
        split2(W1[(2*kw)*64 + n], W1[(2*kw+1)*64 + n], h, l);
        g_W1h[idx] = h; g_W1l[idx] = l;
        return;
    }
    int j = idx - 4096;
    if (j < 65536){                                // W3: [1024 k][128 n] -> [128 n][512 kw]
        int n = j >> 9, kw = j & 511;
        uint32_t h, l;
        split2(W3[(2*kw)*128 + n], W3[(2*kw+1)*128 + n], h, l);
        g_W3h[j] = h; g_W3l[j] = l;
        return;
    }
    int m = j - 65536;
    if (m < 8192){                                 // W4: [128 k][128 n] -> [128 n][64 kw]
        int n = m >> 6, kw = m & 63;
        uint32_t h, l;
        split2(W4[(2*kw)*128 + n], W4[(2*kw+1)*128 + n], h, l);
        g_W4h[m] = h; g_W4l[m] = l;
    }
}

// ---------------- Pass A: GEMM1 (bf16 3-term split, ldmatrix) + leaky + LN + GEMM2 + exp ----------------
// 128 rows / block, 256 threads (8 warps, one 16-row M-tile each, full 64 cols), 2048 blocks.
#define ATT_SMEM_WORDS (8704 + 8704 + 4352 + 4352 + 512 + 64*3 + 8 + 256)

__global__ __launch_bounds__(256) void att_kernel(
    const float* __restrict__ feat,
    const float* __restrict__ b1,
    const float* __restrict__ g1, const float* __restrict__ be1,
    const float* __restrict__ W2, const float* __restrict__ b2)
{
    extern __shared__ uint32_t smw[];
    uint32_t* sAh = smw;                 // 128 x 68 = 8704
    uint32_t* sAl = sAh + 8704;          // 8704
    uint32_t* sWh = sAl + 8704;          // 64 x 68 = 4352
    uint32_t* sWl = sWh + 4352;          // 4352
    float* sW2  = (float*)(sWl + 4352);  // 512
    float* sB1  = sW2 + 512;             // 64
    float* sG1  = sB1 + 64;              // 64
    float* sBe1 = sG1 + 64;              // 64
    float* sB2  = sBe1 + 64;             // 8
    float* sMu  = sB2 + 8;               // 128
    float* sIs  = sMu + 128;             // 128
    float* sH   = (float*)sAh;           // alias, stride 65 (8320 <= 8704)

    int t = threadIdx.x;
    int row0 = blockIdx.x * 128;
    int wid = t >> 5, lane = t & 31;
    int g = lane >> 2, t4 = lane & 3;

    {   // stage A: feat 128x128 -> bf16 hi/lo packed (4096 float4, 16/thread)
        const float4* gsrc = (const float4*)(feat + (size_t)row0 * 128);
        #pragma unroll
        for (int e = 0; e < 16; e++){
            int i4 = t + 256*e;
            int r = i4 >> 5, c4 = i4 & 31;
            float4 a = gsrc[i4];
            uint32_t h0, l0, h1, l1;
            split2(a.x, a.y, h0, l0);
            split2(a.z, a.w, h1, l1);
            int base = r*68 + 2*c4;
            sAh[base] = h0; sAh[base+1] = h1;
            sAl[base] = l0; sAl[base+1] = l1;
        }
    }
    {   // stage B: copy prepacked W1 hi/lo
        #pragma unroll
        for (int e = 0; e < 4; e++){
            int i4 = t + 256*e;
            int n = i4 >> 4, c4 = i4 & 15;
            *(uint4*)&sWh[n*68 + 4*c4] = *(const uint4*)&g_W1h[n*64 + 4*c4];
            *(uint4*)&sWl[n*68 + 4*c4] = *(const uint4*)&g_W1l[n*64 + 4*c4];
        }
    }
    if (t < 128) ((float4*)sW2)[t] = ((const float4*)W2)[t];
    if (t < 64){ sB1[t] = b1[t]; sG1[t] = g1[t]; sBe1[t] = be1[t]; }
    if (t < 8)  sB2[t] = b2[t];
    __syncthreads();

    // GEMM1: warp = rows [wid*16, +16) x all 64 cols. K=128 -> 8 k16-steps.
    int rbase = wid * 16;
    float acc[8][4];
    #pragma unroll
    for (int j = 0; j < 8; j++){ acc[j][0]=acc[j][1]=acc[j][2]=acc[j][3]=0.f; }

    uint32_t aBaseH, aBaseL;
    {
        int rowf = rbase + (lane & 7) + ((lane >> 3) & 1) * 8;
        int kws  = ((lane >> 4) & 1) * 4;
        aBaseH = (uint32_t)__cvta_generic_to_shared(sAh + rowf*68 + kws);
        aBaseL = (uint32_t)__cvta_generic_to_shared(sAl + rowf*68 + kws);
    }
    uint32_t bBaseH[4], bBaseL[4];
    #pragma unroll
    for (int jp = 0; jp < 4; jp++){
        int nf  = (2*jp + ((lane >> 4) & 1)) * 8 + (lane & 7);
        int kws = ((lane >> 3) & 1) * 4;
        bBaseH[jp] = (uint32_t)__cvta_generic_to_shared(sWh + nf*68 + kws);
        bBaseL[jp] = (uint32_t)__cvta_generic_to_shared(sWl + nf*68 + kws);
    }

    #pragma unroll 2
    for (int ks = 0; ks < 8; ks++){
        uint32_t off = (uint32_t)ks * 32;   // 8 words per k16-step
        uint32_t ah0,ah1,ah2,ah3, al0,al1,al2,al3;
        ldsm_x4(ah0,ah1,ah2,ah3, aBaseH + off);
        ldsm_x4(al0,al1,al2,al3, aBaseL + off);
        #pragma unroll
        for (int jp = 0; jp < 4; jp++){
            uint32_t bh0,bh1,bh2,bh3, bl0,bl1,bl2,bl3;
            ldsm_x4(bh0,bh1,bh2,bh3, bBaseH[jp] + off);
            ldsm_x4(bl0,bl1,bl2,bl3, bBaseL[jp] + off);
            mma_bf16(acc[2*jp],   ah0,ah1,ah2,ah3, bh0,bh1);
            mma_bf16(acc[2*jp],   al0,al1,al2,al3, bh0,bh1);
            mma_bf16(acc[2*jp],   ah0,ah1,ah2,ah3, bl0,bl1);
            mma_bf16(acc[2*jp+1], ah0,ah1,ah2,ah3, bh2,bh3);
            mma_bf16(acc[2*jp+1], al0,al1,al2,al3, bh2,bh3);
            mma_bf16(acc[2*jp+1], ah0,ah1,ah2,ah3, bl2,bl3);
        }
    }
    __syncthreads();   // all sAh/sAl reads done before aliasing sAh as sH

    {   // epilogue: bias + leaky -> sH (stride 65)
        int rA = rbase + g, rB = rA + 8;
        #pragma unroll
        for (int j = 0; j < 8; j++){
            int c = j*8 + 2*t4;
            sH[rA*65 + c]     = leaky(acc[j][0] + sB1[c]);
            sH[rA*65 + c + 1] = leaky(acc[j][1] + sB1[c+1]);
            sH[rB*65 + c]     = leaky(acc[j][2] + sB1[c]);
            sH[rB*65 + c + 1] = leaky(acc[j][3] + sB1[c+1]);
        }
    }
    __syncthreads();

    if (t < 128){   // LN stats per row
        float sum = 0.f, ss = 0.f;
        #pragma unroll 8
        for (int j = 0; j < 64; j++){ float v = sH[t*65 + j]; sum += v; ss += v*v; }
        float mu = sum * (1.f/64.f);
        float var = ss * (1.f/64.f) - mu*mu;
        sMu[t] = mu; sIs[t] = rsqrtf(var + EPS);
    }
    __syncthreads();

    {   // GEMM2 (64->8) + exp (fp32, exact)
        int row = t >> 1, half = t & 1, kb = half * 4;
        float mu = sMu[row], is = sIs[row];
        float a0=0.f, a1=0.f, a2=0.f, a3=0.f;
        #pragma unroll 4
        for (int j = 0; j < 64; j++){
            float hn = (sH[row*65 + j] - mu) * is * sG1[j] + sBe1[j];
            a0 += hn * sW2[j*8 + kb + 0];
            a1 += hn * sW2[j*8 + kb + 1];
            a2 += hn * sW2[j*8 + kb + 2];
            a3 += hn * sW2[j*8 + kb + 3];
        }
        int grow = row0 + row;
        float4 o;
        o.x = __expf(a0 + sB2[kb+0]);
        o.y = __expf(a1 + sB2[kb+1]);
        o.z = __expf(a2 + sB2[kb+2]);
        o.w = __expf(a3 + sB2[kb+3]);
        *(float4*)&g_att[grow*8 + kb] = o;
    }
}

// ---------------- Pass B: segment softmax + aggregation, 2 heads/thread ----------------
// 4096 blocks x 256 threads. Thread = (row-group rg, head-pair hp, col-quad cq).
// Each sF float4 is read once per row-group (2x) instead of once per head (8x).
__global__ __launch_bounds__(256) void aggregate_kernel(const float* __restrict__ feat){
    int gi = blockIdx.x;
    __shared__ __align__(16) float sF[32][128];
    __shared__ __align__(16) float sAtt[32][8];
    __shared__ __align__(16) float sRed[128][8];    // rg=1 partial acc
    __shared__ float sS[128][2];                    // rg=1 partial head sums

    int t = threadIdx.x;
    int lo = g_seglo[gi], hi = g_seglo[gi + 1];
    int rg = t >> 7;              // 0 or 1
    int slot = t & 127;
    int hp = slot >> 5;           // head pair 0..3 -> heads 2hp, 2hp+1
    int cq = slot & 31;           // col quad

    float4 acc0 = make_float4(0.f,0.f,0.f,0.f);
    float4 acc1 = make_float4(0.f,0.f,0.f,0.f);
    float ss0 = 0.f, ss1 = 0.f;

    for (int base = lo; base < hi; base += 32){
        int cnt = min(32, hi - base);
        __syncthreads();
        for (int idx4 = t; idx4 < cnt*32; idx4 += 256){
            int r = idx4 >> 5, c4 = idx4 & 31;
            *(float4*)&sF[r][4*c4] = *(const float4*)&feat[(size_t)(base + r) * 128 + 4*c4];
        }
        if (t < cnt*8){
            int r = t >> 3, k = t & 7;
            sAtt[r][k] = g_att[(base + r)*8 + k];
        }
        __syncthreads();
        int rlo = rg * 16, rhi = min(cnt, rlo + 16);
        for (int r = rlo; r < rhi; r++){
            float a0 = sAtt[r][2*hp];
            float a1 = sAtt[r][2*hp + 1];
            ss0 += a0; ss1 += a1;
            float4 f = *(const float4*)&sF[r][cq*4];
            acc0.x += a0*f.x; acc0.y += a0*f.y; acc0.z += a0*f.z; acc0.w += a0*f.w;
            acc1.x += a1*f.x; acc1.y += a1*f.y; acc1.z += a1*f.z; acc1.w += a1*f.w;
        }
    }
    __syncthreads();
    if (rg == 1){
        *(float4*)&sRed[slot][0] = acc0;
        *(float4*)&sRed[slot][4] = acc1;
        sS[slot][0] = ss0; sS[slot][1] = ss1;
    }
    __syncthreads();
    if (rg == 0){
        float4 p0 = *(const float4*)&sRed[slot][0];
        float4 p1 = *(const float4*)&sRed[slot][4];
        acc0.x += p0.x; acc0.y += p0.y; acc0.z += p0.z; acc0.w += p0.w;
        acc1.x += p1.x; acc1.y += p1.y; acc1.z += p1.z; acc1.w += p1.w;
        float tot0 = ss0 + sS[slot][0];
        float tot1 = ss1 + sS[slot][1];
        float inv0 = (hi > lo) ? 1.f / tot0 : 0.f;
        float inv1 = (hi > lo) ? 1.f / tot1 : 0.f;
        acc0.x *= inv0; acc0.y *= inv0; acc0.z *= inv0; acc0.w *= inv0;
        acc1.x *= inv1; acc1.y *= inv1; acc1.z *= inv1; acc1.w *= inv1;
        *(float4*)&g_outflat[(size_t)gi*1024 + (2*hp)*128 + cq*4]     = acc0;
        *(float4*)&g_outflat[(size_t)gi*1024 + (2*hp + 1)*128 + cq*4] = acc1;
    }
}

// ---------------- Pass C: GEMM3(bf16 3-term)+leaky+LN, GEMM4(bf16 3-term)+leaky+LN ----------------
// 16 graphs / block, 256 blocks, 256 threads. Warp w owns n-cols [w*16, +16).
#define FIN_SMEM_WORDS (8704 + 8704 + 1088 + 1088 + 2112 + 128*6 + 32)

__global__ __launch_bounds__(256) void final_kernel(
    const float* __restrict__ b3,
    const float* __restrict__ g3, const float* __restrict__ be3,
    const float* __restrict__ b4,
    const float* __restrict__ g4, const float* __restrict__ be4,
    float* __restrict__ out)
{
    extern __shared__ uint32_t smw[];
    uint32_t* sWh = smw;                 // 128 x 68 = 8704
    uint32_t* sWl = sWh + 8704;          // 8704
    uint32_t* sAh = sWl + 8704;          // 16 x 68 = 1088
    uint32_t* sAl = sAh + 1088;          // 1088
    float* sO1 = (float*)(sAl + 1088);   // 16 x 132 = 2112 (fp32 scratch)
    float* sB3 = sO1 + 2112;
    float* sG3 = sB3 + 128;
    float* sBe3= sG3 + 128;
    float* sB4 = sBe3+ 128;
    float* sG4 = sB4 + 128;
    float* sBe4= sG4 + 128;
    float* sMu = sBe4+ 128;              // 16
    float* sIs = sMu + 16;               // 16

    int t = threadIdx.x;
    int g0 = blockIdx.x * 16;
    int wid = t >> 5, lane = t & 31;
    int g = lane >> 2, t4 = lane & 3;

    if (t < 128){
        sB3[t]=b3[t]; sG3[t]=g3[t]; sBe3[t]=be3[t];
        sB4[t]=b4[t]; sG4[t]=g4[t]; sBe4[t]=be4[t];
    }

    uint32_t aBaseH, aBaseL, bBaseH, bBaseL;
    {
        int rowf = (lane & 7) + ((lane >> 3) & 1) * 8;
        int kwsA = ((lane >> 4) & 1) * 4;
        aBaseH = (uint32_t)__cvta_generic_to_shared(sAh + rowf*68 + kwsA);
        aBaseL = (uint32_t)__cvta_generic_to_shared(sAl + rowf*68 + kwsA);
        int nf   = wid*16 + ((lane >> 4) & 1) * 8 + (lane & 7);
        int kwsB = ((lane >> 3) & 1) * 4;
        bBaseH = (uint32_t)__cvta_generic_to_shared(sWh + nf*68 + kwsB);
        bBaseL = (uint32_t)__cvta_generic_to_shared(sWl + nf*68 + kwsB);
    }

    // ---- GEMM3: [16,1024] @ [1024,128], 8 k-tiles of 128 (8 k16-steps each) ----
    float acc[2][4];
    acc[0][0]=acc[0][1]=acc[0][2]=acc[0][3]=0.f;
    acc[1][0]=acc[1][1]=acc[1][2]=acc[1][3]=0.f;

    for (int kt = 0; kt < 8; kt++){
        __syncthreads();
        {   // stage A slice 16x128 -> bf16 hi/lo (512 float4, 2/thread)
            #pragma unroll
            for (int e = 0; e < 2; e++){
                int i4 = t + 256*e;
                int r = i4 >> 5, c4 = i4 & 31;
                float4 a = *(const float4*)&g_outflat[(size_t)(g0 + r)*1024 + kt*128 + 4*c4];
                uint32_t h0, l0, h1, l1;
                split2(a.x, a.y, h0, l0);
                split2(a.z, a.w, h1, l1);
                int base = r*68 + 2*c4;
                sAh[base] = h0; sAh[base+1] = h1;
                sAl[base] = l0; sAl[base+1] = l1;
            }
        }
        {   // stage W3 hi/lo k-tile
            #pragma unroll
            for (int e = 0; e < 8; e++){
                int i4 = t + 256*e;
                int n = i4 >> 4, c4 = i4 & 15;
                *(uint4*)&sWh[n*68 + 4*c4] = *(const uint4*)&g_W3h[n*512 + kt*64 + 4*c4];
                *(uint4*)&sWl[n*68 + 4*c4] = *(const uint4*)&g_W3l[n*512 + kt*64 + 4*c4];
            }
        }
        __syncthreads();

        #pragma unroll 2
        for (int ks = 0; ks < 8; ks++){
            uint32_t off = (uint32_t)ks * 32;
            uint32_t ah0,ah1,ah2,ah3, al0,al1,al2,al3;
            ldsm_x4(ah0,ah1,ah2,ah3, aBaseH + off);
            ldsm_x4(al0,al1,al2,al3, aBaseL + off);
            uint32_t bh0,bh1,bh2,bh3, bl0,bl1,bl2,bl3;
            ldsm_x4(bh0,bh1,bh2,bh3, bBaseH + off);
            ldsm_x4(bl0,bl1,bl2,bl3, bBaseL + off);
            mma_bf16(acc[0], ah0,ah1,ah2,ah3, bh0,bh1);
            mma_bf16(acc[0], al0,al1,al2,al3, bh0,bh1);
            mma_bf16(acc[0], ah0,ah1,ah2,ah3, bl0,bl1);
            mma_bf16(acc[1], ah0,ah1,ah2,ah3, bh2,bh3);
            mma_bf16(acc[1], al0,al1,al2,al3, bh2,bh3);
            mma_bf16(acc[1], ah0,ah1,ah2,ah3, bl2,bl3);
        }
    }
    __syncthreads();

    {   // epilogue GEMM3 -> sO1 (fp32); stage W4 hi/lo into sWh/sWl
        #pragma unroll
        for (int jj = 0; jj < 2; jj++){
            int c = wid*16 + jj*8 + 2*t4;
            sO1[g*132 + c]       = leaky(acc[jj][0] + sB3[c]);
            sO1[g*132 + c + 1]   = leaky(acc[jj][1] + sB3[c+1]);
            sO1[(g+8)*132 + c]   = leaky(acc[jj][2] + sB3[c]);
            sO1[(g+8)*132 + c+1] = leaky(acc[jj][3] + sB3[c+1]);
        }
        #pragma unroll
        for (int e = 0; e < 8; e++){
            int i4 = t + 256*e;
            int n = i4 >> 4, c4 = i4 & 15;
            *(uint4*)&sWh[n*68 + 4*c4] = *(const uint4*)&g_W4h[n*64 + 4*c4];
            *(uint4*)&sWl[n*68 + 4*c4] = *(const uint4*)&g_W4l[n*64 + 4*c4];
        }
    }
    __syncthreads();

    if (t < 16){   // LN1 stats
        float sum = 0.f, ss = 0.f;
        #pragma unroll 8
        for (int j = 0; j < 128; j++){ float v = sO1[t*132 + j]; sum += v; ss += v*v; }
        float mu = sum * (1.f/128.f);
        float var = ss * (1.f/128.f) - mu*mu;
        sMu[t] = mu; sIs[t] = rsqrtf(var + EPS);
    }
    __syncthreads();
    {   // LN1 apply + bf16 split into sAh/sAl (1024 words, 4/thread)
        #pragma unroll
        for (int e = 0; e < 4; e++){
            int w = t + 256*e;
            int r = w >> 6, kw = w & 63;
            int c = 2*kw;
            float mu = sMu[r], is = sIs[r];
            float v0 = (sO1[r*132 + c]     - mu) * is * sG3[c]   + sBe3[c];
            float v1 = (sO1[r*132 + c + 1] - mu) * is * sG3[c+1] + sBe3[c+1];
            uint32_t h, l;
            split2(v0, v1, h, l);
            sAh[r*68 + kw] = h;
            sAl[r*68 + kw] = l;
        }
    }
    __syncthreads();

    // ---- GEMM4: [16,128] @ [128,128] (8 k16-steps) ----
    float acc2[2][4];
    acc2[0][0]=acc2[0][1]=acc2[0][2]=acc2[0][3]=0.f;
    acc2[1][0]=acc2[1][1]=acc2[1][2]=acc2[1][3]=0.f;

    #pragma unroll 2
    for (int ks = 0; ks < 8; ks++){
        uint32_t off = (uint32_t)ks * 32;
        uint32_t ah0,ah1,ah2,ah3, al0,al1,al2,al3;
        ldsm_x4(ah0,ah1,ah2,ah3, aBaseH + off);
        ldsm_x4(al0,al1,al2,al3, aBaseL + off);
        uint32_t bh0,bh1,bh2,bh3, bl0,bl1,bl2,bl3;
        ldsm_x4(bh0,bh1,bh2,bh3, bBaseH + off);
        ldsm_x4(bl0,bl1,bl2,bl3, bBaseL + off);
        mma_bf16(acc2[0], ah0,ah1,ah2,ah3, bh0,bh1);
        mma_bf16(acc2[0], al0,al1,al2,al3, bh0,bh1);
        mma_bf16(acc2[0], ah0,ah1,ah2,ah3, bl0,bl1);
        mma_bf16(acc2[1], ah0,ah1,ah2,ah3, bh2,bh3);
        mma_bf16(acc2[1], al0,al1,al2,al3, bh2,bh3);
        mma_bf16(acc2[1], ah0,ah1,ah2,ah3, bl2,bl3);
    }
    __syncthreads();

    // epilogue GEMM4 -> sO1 (reuse as sO2)
    #pragma unroll
    for (int jj = 0; jj < 2; jj++){
        int c = wid*16 + jj*8 + 2*t4;
        sO1[g*132 + c]       = leaky(acc2[jj][0] + sB4[c]);
        sO1[g*132 + c + 1]   = leaky(acc2[jj][1] + sB4[c+1]);
        sO1[(g+8)*132 + c]   = leaky(acc2[jj][2] + sB4[c]);
        sO1[(g+8)*132 + c+1] = leaky(acc2[jj][3] + sB4[c+1]);
    }
    __syncthreads();

    if (t < 16){   // LN2 stats
        float sum = 0.f, ss = 0.f;
        #pragma unroll 8
        for (int j = 0; j < 128; j++){ float v = sO1[t*132 + j]; sum += v; ss += v*v; }
        float mu = sum * (1.f/128.f);
        float var = ss * (1.f/128.f) - mu*mu;
        sMu[t] = mu; sIs[t] = rsqrtf(var + EPS);
    }
    __syncthreads();
    #pragma unroll
    for (int e = 0; e < 8; e++){
        int idx = t + 256*e;
        int r = idx >> 7, c = idx & 127;
        out[(g0 + r)*128 + c] = (sO1[r*132 + c] - sMu[r]) * sIs[r] * sG4[c] + sBe4[c];
    }
}

// ---------------- host ----------------
extern "C" void kernel_launch(void* const* d_in, const int* in_sizes, int n_in,
                              void* d_out, int out_size)
{
    const float* feat = (const float*)d_in[0];
    const int*   batch = (const int*)d_in[1];
    const float* W1 = (const float*)d_in[2];
    const float* b1 = (const float*)d_in[3];
    const float* g1 = (const float*)d_in[4];
    const float* be1= (const float*)d_in[5];
    const float* W2 = (const float*)d_in[6];
    const float* b2 = (const float*)d_in[7];
    const float* W3 = (const float*)d_in[8];
    const float* b3 = (const float*)d_in[9];
    const float* g3 = (const float*)d_in[10];
    const float* be3= (const float*)d_in[11];
    const float* W4 = (const float*)d_in[12];
    const float* b4 = (const float*)d_in[13];
    const float* g4 = (const float*)d_in[14];
    const float* be4= (const float*)d_in[15];

    int nrows = in_sizes[0] / 128;

    const int att_smem = ATT_SMEM_WORDS * 4;   // 108,320 B -> 2 CTAs/SM
    const int fin_smem = FIN_SMEM_WORDS * 4;   //  89,984 B -> 2 CTAs/SM
    cudaFuncSetAttribute(att_kernel,   cudaFuncAttributeMaxDynamicSharedMemorySize, att_smem);
    cudaFuncSetAttribute(final_kernel, cudaFuncAttributeMaxDynamicSharedMemorySize, fin_smem);

    detect_kernel<<<1, 256>>>(batch, nrows);
    bounds_kernel<<<NGRAPH / 256, 256>>>(batch, nrows);
    prep_kernel<<<304, 256>>>(W1, W3, W4);
    att_kernel<<<nrows / 128, 256, att_smem>>>(feat, b1, g1, be1, W2, b2);
    aggregate_kernel<<<NGRAPH, 256>>>(feat);
    final_kernel<<<NGRAPH / 16, 256, fin_smem>>>(b3, g3, be3, b4, g4, be4, (float*)d_out);
}

// round 15
// speedup vs baseline: 1.5949x; 1.0089x over previous
#include <cuda_runtime.h>
#include <cuda_bf16.h>
#include <cstdint>

#define NGRAPH 4096
#define EPS 1e-6f

// ---------------- device scratch ----------------
__device__ __align__(16) float g_att[262144 * 8];          // exp attention, unnormalized [N,8]
__device__ __align__(16) float g_outflat[NGRAPH * 1024];   // aggregated [B, H*D]
__device__ __align__(16) unsigned int g_W1h[64 * 64];      // W1 packed bf16x2 [n][kw]
__device__ __align__(16) unsigned int g_W1l[64 * 64];
__device__ __align__(16) unsigned int g_W3h[128 * 512];    // W3 packed [n][kw]
__device__ __align__(16) unsigned int g_W3l[128 * 512];
__device__ __align__(16) unsigned int g_W4h[128 * 64];     // W4 packed [n][kw]
__device__ __align__(16) unsigned int g_W4l[128 * 64];
__device__ int g_seglo[NGRAPH + 1];
__device__ int g_is64;

__device__ __forceinline__ float leaky(float x){ return x > 0.f ? x : 0.01f * x; }

// split (x,y) into bf16 hi/lo pairs packed as bf16x2 words (x in LOW half).
__device__ __forceinline__ void split2(float x, float y, uint32_t& h, uint32_t& l){
    __nv_bfloat16 hx = __float2bfloat16_rn(x);
    __nv_bfloat16 hy = __float2bfloat16_rn(y);
    float rx = x - __bfloat162float(hx);
    float ry = y - __bfloat162float(hy);
    __nv_bfloat162 hh = __halves2bfloat162(hx, hy);           // .x = low half
    __nv_bfloat162 ll = __halves2bfloat162(__float2bfloat16_rn(rx), __float2bfloat16_rn(ry));
    h = *reinterpret_cast<uint32_t*>(&hh);
    l = *reinterpret_cast<uint32_t*>(&ll);
}

// D += A(16x16 bf16) * B(16x8 bf16), fp32 accumulate
__device__ __forceinline__ void mma_bf16(float* c,
    uint32_t a0, uint32_t a1, uint32_t a2, uint32_t a3, uint32_t b0, uint32_t b1){
    asm volatile(
      "mma.sync.aligned.m16n8k16.row.col.f32.bf16.bf16.f32 "
      "{%0,%1,%2,%3}, {%4,%5,%6,%7}, {%8,%9}, {%0,%1,%2,%3};\n"
      : "+f"(c[0]), "+f"(c[1]), "+f"(c[2]), "+f"(c[3])
      : "r"(a0), "r"(a1), "r"(a2), "r"(a3), "r"(b0), "r"(b1));
}

// ldmatrix x4 (non-transposed, b16)
__device__ __forceinline__ void ldsm_x4(uint32_t& r0, uint32_t& r1, uint32_t& r2, uint32_t& r3,
                                        uint32_t addr){
    asm volatile("ldmatrix.sync.aligned.m8n8.x4.shared.b16 {%0,%1,%2,%3}, [%4];"
        : "=r"(r0), "=r"(r1), "=r"(r2), "=r"(r3) : "r"(addr));
}

// Parallel batch dtype detection (int32 loads only).
__global__ void detect_kernel(const int* __restrict__ batch, int n){
    __shared__ int bad;
    if (threadIdx.x == 0) bad = 0;
    __syncthreads();
    int base = n / 2;
    int i = threadIdx.x;
    int lo = batch[base + 2*i];
    int hi = batch[base + 2*i + 1];
    if (hi != 0 || lo < 0 || lo >= NGRAPH) bad = 1;
    __syncthreads();
    if (threadIdx.x == 0) g_is64 = (bad == 0);
}

__device__ __forceinline__ int bat(const int* b, int i, int is64){
    return is64 ? b[2*i] : b[i];
}

__device__ __forceinline__ int lbound(const int* b, int n, int val, int is64){
    int lo = 0, hi = n;
    while (lo < hi){
        int mid = (lo + hi) >> 1;
        if (bat(b, mid, is64) < val) lo = mid + 1; else hi = mid;
    }
    return lo;
}

// ---------------- segment bounds: one thread per graph ----------------
__global__ void bounds_kernel(const int* __restrict__ batch, int n){
    int g = blockIdx.x * 256 + threadIdx.x;
    int is64 = g_is64;
    if (g < NGRAPH) g_seglo[g] = lbound(batch, n, g, is64);
    if (g == 0)     g_seglo[NGRAPH] = n;
}

// ---------------- weight prep: pack W1/W3/W4 as bf16x2 hi/lo, [n][kword] ----------------
__global__ void prep_kernel(const float* __restrict__ W1,
                            const float* __restrict__ W3,
                            const float* __restrict__ W4){
    int idx = blockIdx.x * 256 + threadIdx.x;
    if (idx < 4096){                               // W1: [128 k][64 n] -> [64 n][64 kw]
        int n = idx >> 6, kw = idx & 63;
        uint32_t h, l;
        split2(W1[(2*kw)*64 + n], W1[(2*kw+1)*64 + n], h, l);
        g_W1h[idx] = h; g_W1l[idx] = l;
        return;
    }
    int j = idx - 4096;
    if (j < 65536){                                // W3: [1024 k][128 n] -> [128 n][512 kw]
        int n = j >> 9, kw = j & 511;
        uint32_t h, l;
        split2(W3[(2*kw)*128 + n], W3[(2*kw+1)*128 + n], h, l);
        g_W3h[j] = h; g_W3l[j] = l;
        return;
    }
    int m = j - 65536;
    if (m < 8192){                                 // W4: [128 k][128 n] -> [128 n][64 kw]
        int n = m >> 6, kw = m & 63;
        uint32_t h, l;
        split2(W4[(2*kw)*128 + n], W4[(2*kw+1)*128 + n], h, l);
        g_W4h[m] = h; g_W4l[m] = l;
    }
}

// ---------------- Pass A: GEMM1 (bf16 3-term, ldmatrix, 4m x 2n warps) + leaky + LN + GEMM2 + exp ----
// 128 rows / block, 256 threads, 2048 blocks.
// Warp (mw, nw): rows [mw*32, +32), cols [nw*32, +32). Halves B smem redundancy vs 8m x 1n.
#define ATT_SMEM_WORDS (8704 + 8704 + 4352 + 4352 + 512 + 64*3 + 8 + 256)

__global__ __launch_bounds__(256) void att_kernel(
    const float* __restrict__ feat,
    const float* __restrict__ b1,
    const float* __restrict__ g1, const float* __restrict__ be1,
    const float* __restrict__ W2, const float* __restrict__ b2)
{
    extern __shared__ uint32_t smw[];
    uint32_t* sAh = smw;                 // 128 x 68 = 8704
    uint32_t* sAl = sAh + 8704;          // 8704
    uint32_t* sWh = sAl + 8704;          // 64 x 68 = 4352
    uint32_t* sWl = sWh + 4352;          // 4352
    float* sW2  = (float*)(sWl + 4352);  // 512
    float* sB1  = sW2 + 512;             // 64
    float* sG1  = sB1 + 64;              // 64
    float* sBe1 = sG1 + 64;              // 64
    float* sB2  = sBe1 + 64;             // 8
    float* sMu  = sB2 + 8;               // 128
    float* sIs  = sMu + 128;             // 128
    float* sH   = (float*)sAh;           // alias, stride 65 (8320 <= 8704)

    int t = threadIdx.x;
    int row0 = blockIdx.x * 128;
    int wid = t >> 5, lane = t & 31;
    int g = lane >> 2, t4 = lane & 3;
    int mw = wid & 3, nw = wid >> 2;

    {   // stage A: feat 128x128 -> bf16 hi/lo packed (4096 float4, 16/thread), STS.64
        const float4* gsrc = (const float4*)(feat + (size_t)row0 * 128);
        #pragma unroll
        for (int e = 0; e < 16; e++){
            int i4 = t + 256*e;
            int r = i4 >> 5, c4 = i4 & 31;
            float4 a = gsrc[i4];
            uint2 h, l;
            split2(a.x, a.y, h.x, l.x);
            split2(a.z, a.w, h.y, l.y);
            int base = r*68 + 2*c4;
            *(uint2*)&sAh[base] = h;
            *(uint2*)&sAl[base] = l;
        }
    }
    {   // stage B: copy prepacked W1 hi/lo
        #pragma unroll
        for (int e = 0; e < 4; e++){
            int i4 = t + 256*e;
            int n = i4 >> 4, c4 = i4 & 15;
            *(uint4*)&sWh[n*68 + 4*c4] = *(const uint4*)&g_W1h[n*64 + 4*c4];
            *(uint4*)&sWl[n*68 + 4*c4] = *(const uint4*)&g_W1l[n*64 + 4*c4];
        }
    }
    if (t < 128) ((float4*)sW2)[t] = ((const float4*)W2)[t];
    if (t < 64){ sB1[t] = b1[t]; sG1[t] = g1[t]; sBe1[t] = be1[t]; }
    if (t < 8)  sB2[t] = b2[t];
    __syncthreads();

    // GEMM1: warp = rows [mw*32,+32) x cols [nw*32,+32). K=128 -> 8 k16-steps.
    float acc[2][4][4];
    #pragma unroll
    for (int mt = 0; mt < 2; mt++)
        #pragma unroll
        for (int jn = 0; jn < 4; jn++){
            acc[mt][jn][0]=0.f; acc[mt][jn][1]=0.f; acc[mt][jn][2]=0.f; acc[mt][jn][3]=0.f;
        }

    uint32_t aBaseH[2], aBaseL[2];
    #pragma unroll
    for (int mt = 0; mt < 2; mt++){
        int rowf = mw*32 + mt*16 + (lane & 7) + ((lane >> 3) & 1) * 8;
        int kws  = ((lane >> 4) & 1) * 4;
        aBaseH[mt] = (uint32_t)__cvta_generic_to_shared(sAh + rowf*68 + kws);
        aBaseL[mt] = (uint32_t)__cvta_generic_to_shared(sAl + rowf*68 + kws);
    }
    uint32_t bBaseH[2], bBaseL[2];
    #pragma unroll
    for (int jp = 0; jp < 2; jp++){
        int nf  = nw*32 + (2*jp + ((lane >> 4) & 1)) * 8 + (lane & 7);
        int kws = ((lane >> 3) & 1) * 4;
        bBaseH[jp] = (uint32_t)__cvta_generic_to_shared(sWh + nf*68 + kws);
        bBaseL[jp] = (uint32_t)__cvta_generic_to_shared(sWl + nf*68 + kws);
    }

    #pragma unroll 2
    for (int ks = 0; ks < 8; ks++){
        uint32_t off = (uint32_t)ks * 32;   // 8 words per k16-step
        uint32_t ah[2][4], al[2][4];
        #pragma unroll
        for (int mt = 0; mt < 2; mt++){
            ldsm_x4(ah[mt][0],ah[mt][1],ah[mt][2],ah[mt][3], aBaseH[mt] + off);
            ldsm_x4(al[mt][0],al[mt][1],al[mt][2],al[mt][3], aBaseL[mt] + off);
        }
        #pragma unroll
        for (int jp = 0; jp < 2; jp++){
            uint32_t bh0,bh1,bh2,bh3, bl0,bl1,bl2,bl3;
            ldsm_x4(bh0,bh1,bh2,bh3, bBaseH[jp] + off);
            ldsm_x4(bl0,bl1,bl2,bl3, bBaseL[jp] + off);
            #pragma unroll
            for (int mt = 0; mt < 2; mt++){
                mma_bf16(acc[mt][2*jp],   ah[mt][0],ah[mt][1],ah[mt][2],ah[mt][3], bh0,bh1);
                mma_bf16(acc[mt][2*jp],   al[mt][0],al[mt][1],al[mt][2],al[mt][3], bh0,bh1);
                mma_bf16(acc[mt][2*jp],   ah[mt][0],ah[mt][1],ah[mt][2],ah[mt][3], bl0,bl1);
                mma_bf16(acc[mt][2*jp+1], ah[mt][0],ah[mt][1],ah[mt][2],ah[mt][3], bh2,bh3);
                mma_bf16(acc[mt][2*jp+1], al[mt][0],al[mt][1],al[mt][2],al[mt][3], bh2,bh3);
                mma_bf16(acc[mt][2*jp+1], ah[mt][0],ah[mt][1],ah[mt][2],ah[mt][3], bl2,bl3);
            }
        }
    }
    __syncthreads();   // all sAh/sAl reads done before aliasing sAh as sH

    {   // epilogue: bias + leaky -> sH (stride 65)
        #pragma unroll
        for (int mt = 0; mt < 2; mt++){
            int rA = mw*32 + mt*16 + g, rB = rA + 8;
            #pragma unroll
            for (int jn = 0; jn < 4; jn++){
                int c = nw*32 + jn*8 + 2*t4;
                sH[rA*65 + c]     = leaky(acc[mt][jn][0] + sB1[c]);
                sH[rA*65 + c + 1] = leaky(acc[mt][jn][1] + sB1[c+1]);
                sH[rB*65 + c]     = leaky(acc[mt][jn][2] + sB1[c]);
                sH[rB*65 + c + 1] = leaky(acc[mt][jn][3] + sB1[c+1]);
            }
        }
    }
    __syncthreads();

    if (t < 128){   // LN stats per row
        float sum = 0.f, ss = 0.f;
        #pragma unroll 8
        for (int j = 0; j < 64; j++){ float v = sH[t*65 + j]; sum += v; ss += v*v; }
        float mu = sum * (1.f/64.f);
        float var = ss * (1.f/64.f) - mu*mu;
        sMu[t] = mu; sIs[t] = rsqrtf(var + EPS);
    }
    __syncthreads();

    {   // GEMM2 (64->8) + exp (fp32, exact)
        int row = t >> 1, half = t & 1, kb = half * 4;
        float mu = sMu[row], is = sIs[row];
        float a0=0.f, a1=0.f, a2=0.f, a3=0.f;
        #pragma unroll 4
        for (int j = 0; j < 64; j++){
            float hn = (sH[row*65 + j] - mu) * is * sG1[j] + sBe1[j];
            a0 += hn * sW2[j*8 + kb + 0];
            a1 += hn * sW2[j*8 + kb + 1];
            a2 += hn * sW2[j*8 + kb + 2];
            a3 += hn * sW2[j*8 + kb + 3];
        }
        int grow = row0 + row;
        float4 o;
        o.x = __expf(a0 + sB2[kb+0]);
        o.y = __expf(a1 + sB2[kb+1]);
        o.z = __expf(a2 + sB2[kb+2]);
        o.w = __expf(a3 + sB2[kb+3]);
        *(float4*)&g_att[grow*8 + kb] = o;
    }
}

// ---------------- Pass B: segment softmax + aggregation, 2 heads/thread ----------------
__global__ __launch_bounds__(256) void aggregate_kernel(const float* __restrict__ feat){
    int gi = blockIdx.x;
    __shared__ __align__(16) float sF[32][128];
    __shared__ __align__(16) float sAtt[32][8];
    __shared__ __align__(16) float sRed[128][8];    // rg=1 partial acc
    __shared__ float sS[128][2];                    // rg=1 partial head sums

    int t = threadIdx.x;
    int lo = g_seglo[gi], hi = g_seglo[gi + 1];
    int rg = t >> 7;              // 0 or 1
    int slot = t & 127;
    int hp = slot >> 5;           // head pair 0..3 -> heads 2hp, 2hp+1
    int cq = slot & 31;           // col quad

    float4 acc0 = make_float4(0.f,0.f,0.f,0.f);
    float4 acc1 = make_float4(0.f,0.f,0.f,0.f);
    float ss0 = 0.f, ss1 = 0.f;

    for (int base = lo; base < hi; base += 32){
        int cnt = min(32, hi - base);
        __syncthreads();
        for (int idx4 = t; idx4 < cnt*32; idx4 += 256){
            int r = idx4 >> 5, c4 = idx4 & 31;
            *(float4*)&sF[r][4*c4] = *(const float4*)&feat[(size_t)(base + r) * 128 + 4*c4];
        }
        if (t < cnt*8){
            int r = t >> 3, k = t & 7;
            sAtt[r][k] = g_att[(base + r)*8 + k];
        }
        __syncthreads();
        int rlo = rg * 16, rhi = min(cnt, rlo + 16);
        for (int r = rlo; r < rhi; r++){
            float a0 = sAtt[r][2*hp];
            float a1 = sAtt[r][2*hp + 1];
            ss0 += a0; ss1 += a1;
            float4 f = *(const float4*)&sF[r][cq*4];
            acc0.x += a0*f.x; acc0.y += a0*f.y; acc0.z += a0*f.z; acc0.w += a0*f.w;
            acc1.x += a1*f.x; acc1.y += a1*f.y; acc1.z += a1*f.z; acc1.w += a1*f.w;
        }
    }
    __syncthreads();
    if (rg == 1){
        *(float4*)&sRed[slot][0] = acc0;
        *(float4*)&sRed[slot][4] = acc1;
        sS[slot][0] = ss0; sS[slot][1] = ss1;
    }
    __syncthreads();
    if (rg == 0){
        float4 p0 = *(const float4*)&sRed[slot][0];
        float4 p1 = *(const float4*)&sRed[slot][4];
        acc0.x += p0.x; acc0.y += p0.y; acc0.z += p0.z; acc0.w += p0.w;
        acc1.x += p1.x; acc1.y += p1.y; acc1.z += p1.z; acc1.w += p1.w;
        float tot0 = ss0 + sS[slot][0];
        float tot1 = ss1 + sS[slot][1];
        float inv0 = (hi > lo) ? 1.f / tot0 : 0.f;
        float inv1 = (hi > lo) ? 1.f / tot1 : 0.f;
        acc0.x *= inv0; acc0.y *= inv0; acc0.z *= inv0; acc0.w *= inv0;
        acc1.x *= inv1; acc1.y *= inv1; acc1.z *= inv1; acc1.w *= inv1;
        *(float4*)&g_outflat[(size_t)gi*1024 + (2*hp)*128 + cq*4]     = acc0;
        *(float4*)&g_outflat[(size_t)gi*1024 + (2*hp + 1)*128 + cq*4] = acc1;
    }
}

// ---------------- Pass C: GEMM3(bf16 3-term)+leaky+LN, GEMM4(bf16 3-term)+leaky+LN ----------------
// 16 graphs / block, 256 blocks, 256 threads. Warp w owns n-cols [w*16, +16).
#define FIN_SMEM_WORDS (8704 + 8704 + 1088 + 1088 + 2112 + 128*6 + 32)

__global__ __launch_bounds__(256) void final_kernel(
    const float* __restrict__ b3,
    const float* __restrict__ g3, const float* __restrict__ be3,
    const float* __restrict__ b4,
    const float* __restrict__ g4, const float* __restrict__ be4,
    float* __restrict__ out)
{
    extern __shared__ uint32_t smw[];
    uint32_t* sWh = smw;                 // 128 x 68 = 8704
    uint32_t* sWl = sWh + 8704;          // 8704
    uint32_t* sAh = sWl + 8704;          // 16 x 68 = 1088
    uint32_t* sAl = sAh + 1088;          // 1088
    float* sO1 = (float*)(sAl + 1088);   // 16 x 132 = 2112 (fp32 scratch)
    float* sB3 = sO1 + 2112;
    float* sG3 = sB3 + 128;
    float* sBe3= sG3 + 128;
    float* sB4 = sBe3+ 128;
    float* sG4 = sB4 + 128;
    float* sBe4= sG4 + 128;
    float* sMu = sBe4+ 128;              // 16
    float* sIs = sMu + 16;               // 16

    int t = threadIdx.x;
    int g0 = blockIdx.x * 16;
    int wid = t >> 5, lane = t & 31;
    int g = lane >> 2, t4 = lane & 3;

    if (t < 128){
        sB3[t]=b3[t]; sG3[t]=g3[t]; sBe3[t]=be3[t];
        sB4[t]=b4[t]; sG4[t]=g4[t]; sBe4[t]=be4[t];
    }

    uint32_t aBaseH, aBaseL, bBaseH, bBaseL;
    {
        int rowf = (lane & 7) + ((lane >> 3) & 1) * 8;
        int kwsA = ((lane >> 4) & 1) * 4;
        aBaseH = (uint32_t)__cvta_generic_to_shared(sAh + rowf*68 + kwsA);
        aBaseL = (uint32_t)__cvta_generic_to_shared(sAl + rowf*68 + kwsA);
        int nf   = wid*16 + ((lane >> 4) & 1) * 8 + (lane & 7);
        int kwsB = ((lane >> 3) & 1) * 4;
        bBaseH = (uint32_t)__cvta_generic_to_shared(sWh + nf*68 + kwsB);
        bBaseL = (uint32_t)__cvta_generic_to_shared(sWl + nf*68 + kwsB);
    }

    // ---- GEMM3: [16,1024] @ [1024,128], 8 k-tiles of 128 (8 k16-steps each) ----
    float acc[2][4];
    acc[0][0]=acc[0][1]=acc[0][2]=acc[0][3]=0.f;
    acc[1][0]=acc[1][1]=acc[1][2]=acc[1][3]=0.f;

    for (int kt = 0; kt < 8; kt++){
        __syncthreads();
        {   // stage A slice 16x128 -> bf16 hi/lo (512 float4, 2/thread)
            #pragma unroll
            for (int e = 0; e < 2; e++){
                int i4 = t + 256*e;
                int r = i4 >> 5, c4 = i4 & 31;
                float4 a = *(const float4*)&g_outflat[(size_t)(g0 + r)*1024 + kt*128 + 4*c4];
                uint2 h, l;
                split2(a.x, a.y, h.x, l.x);
                split2(a.z, a.w, h.y, l.y);
                int base = r*68 + 2*c4;
                *(uint2*)&sAh[base] = h;
                *(uint2*)&sAl[base] = l;
            }
        }
        {   // stage W3 hi/lo k-tile
            #pragma unroll
            for (int e = 0; e < 8; e++){
                int i4 = t + 256*e;
                int n = i4 >> 4, c4 = i4 & 15;
                *(uint4*)&sWh[n*68 + 4*c4] = *(const uint4*)&g_W3h[n*512 + kt*64 + 4*c4];
                *(uint4*)&sWl[n*68 + 4*c4] = *(const uint4*)&g_W3l[n*512 + kt*64 + 4*c4];
            }
        }
        __syncthreads();

        #pragma unroll 2
        for (int ks = 0; ks < 8; ks++){
            uint32_t off = (uint32_t)ks * 32;
            uint32_t ah0,ah1,ah2,ah3, al0,al1,al2,al3;
            ldsm_x4(ah0,ah1,ah2,ah3, aBaseH + off);
            ldsm_x4(al0,al1,al2,al3, aBaseL + off);
            uint32_t bh0,bh1,bh2,bh3, bl0,bl1,bl2,bl3;
            ldsm_x4(bh0,bh1,bh2,bh3, bBaseH + off);
            ldsm_x4(bl0,bl1,bl2,bl3, bBaseL + off);
            mma_bf16(acc[0], ah0,ah1,ah2,ah3, bh0,bh1);
            mma_bf16(acc[0], al0,al1,al2,al3, bh0,bh1);
            mma_bf16(acc[0], ah0,ah1,ah2,ah3, bl0,bl1);
            mma_bf16(acc[1], ah0,ah1,ah2,ah3, bh2,bh3);
            mma_bf16(acc[1], al0,al1,al2,al3, bh2,bh3);
            mma_bf16(acc[1], ah0,ah1,ah2,ah3, bl2,bl3);
        }
    }
    __syncthreads();

    {   // epilogue GEMM3 -> sO1 (fp32); stage W4 hi/lo into sWh/sWl
        #pragma unroll
        for (int jj = 0; jj < 2; jj++){
            int c = wid*16 + jj*8 + 2*t4;
            sO1[g*132 + c]       = leaky(acc[jj][0] + sB3[c]);
            sO1[g*132 + c + 1]   = leaky(acc[jj][1] + sB3[c+1]);
            sO1[(g+8)*132 + c]   = leaky(acc[jj][2] + sB3[c]);
            sO1[(g+8)*132 + c+1] = leaky(acc[jj][3] + sB3[c+1]);
        }
        #pragma unroll
        for (int e = 0; e < 8; e++){
            int i4 = t + 256*e;
            int n = i4 >> 4, c4 = i4 & 15;
            *(uint4*)&sWh[n*68 + 4*c4] = *(const uint4*)&g_W4h[n*64 + 4*c4];
            *(uint4*)&sWl[n*68 + 4*c4] = *(const uint4*)&g_W4l[n*64 + 4*c4];
        }
    }
    __syncthreads();

    if (t < 16){   // LN1 stats
        float sum = 0.f, ss = 0.f;
        #pragma unroll 8
        for (int j = 0; j < 128; j++){ float v = sO1[t*132 + j]; sum += v; ss += v*v; }
        float mu = sum * (1.f/128.f);
        float var = ss * (1.f/128.f) - mu*mu;
        sMu[t] = mu; sIs[t] = rsqrtf(var + EPS);
    }
    __syncthreads();
    {   // LN1 apply + bf16 split into sAh/sAl (1024 words, 4/thread)
        #pragma unroll
        for (int e = 0; e < 4; e++){
            int w = t + 256*e;
            int r = w >> 6, kw = w & 63;
            int c = 2*kw;
            float mu = sMu[r], is = sIs[r];
            float v0 = (sO1[r*132 + c]     - mu) * is * sG3[c]   + sBe3[c];
            float v1 = (sO1[r*132 + c + 1] - mu) * is * sG3[c+1] + sBe3[c+1];
            uint32_t h, l;
            split2(v0, v1, h, l);
            sAh[r*68 + kw] = h;
            sAl[r*68 + kw] = l;
        }
    }
    __syncthreads();

    // ---- GEMM4: [16,128] @ [128,128] (8 k16-steps) ----
    float acc2[2][4];
    acc2[0][0]=acc2[0][1]=acc2[0][2]=acc2[0][3]=0.f;
    acc2[1][0]=acc2[1][1]=acc2[1][2]=acc2[1][3]=0.f;

    #pragma unroll 2
    for (int ks = 0; ks < 8; ks++){
        uint32_t off = (uint32_t)ks * 32;
        uint32_t ah0,ah1,ah2,ah3, al0,al1,al2,al3;
        ldsm_x4(ah0,ah1,ah2,ah3, aBaseH + off);
        ldsm_x4(al0,al1,al2,al3, aBaseL + off);
        uint32_t bh0,bh1,bh2,bh3, bl0,bl1,bl2,bl3;
        ldsm_x4(bh0,bh1,bh2,bh3, bBaseH + off);
        ldsm_x4(bl0,bl1,bl2,bl3, bBaseL + off);
        mma_bf16(acc2[0], ah0,ah1,ah2,ah3, bh0,bh1);
        mma_bf16(acc2[0], al0,al1,al2,al3, bh0,bh1);
        mma_bf16(acc2[0], ah0,ah1,ah2,ah3, bl0,bl1);
        mma_bf16(acc2[1], ah0,ah1,ah2,ah3, bh2,bh3);
        mma_bf16(acc2[1], al0,al1,al2,al3, bh2,bh3);
        mma_bf16(acc2[1], ah0,ah1,ah2,ah3, bl2,bl3);
    }
    __syncthreads();

    // epilogue GEMM4 -> sO1 (reuse as sO2)
    #pragma unroll
    for (int jj = 0; jj < 2; jj++){
        int c = wid*16 + jj*8 + 2*t4;
        sO1[g*132 + c]       = leaky(acc2[jj][0] + sB4[c]);
        sO1[g*132 + c + 1]   = leaky(acc2[jj][1] + sB4[c+1]);
        sO1[(g+8)*132 + c]   = leaky(acc2[jj][2] + sB4[c]);
        sO1[(g+8)*132 + c+1] = leaky(acc2[jj][3] + sB4[c+1]);
    }
    __syncthreads();

    if (t < 16){   // LN2 stats
        float sum = 0.f, ss = 0.f;
        #pragma unroll 8
        for (int j = 0; j < 128; j++){ float v = sO1[t*132 + j]; sum += v; ss += v*v; }
        float mu = sum * (1.f/128.f);
        float var = ss * (1.f/128.f) - mu*mu;
        sMu[t] = mu; sIs[t] = rsqrtf(var + EPS);
    }
    __syncthreads();
    #pragma unroll
    for (int e = 0; e < 8; e++){
        int idx = t + 256*e;
        int r = idx >> 7, c = idx & 127;
        out[(g0 + r)*128 + c] = (sO1[r*132 + c] - sMu[r]) * sIs[r] * sG4[c] + sBe4[c];
    }
}

// ---------------- host ----------------
extern "C" void kernel_launch(void* const* d_in, const int* in_sizes, int n_in,
                              void* d_out, int out_size)
{
    const float* feat = (const float*)d_in[0];
    const int*   batch = (const int*)d_in[1];
    const float* W1 = (const float*)d_in[2];
    const float* b1 = (const float*)d_in[3];
    const float* g1 = (const float*)d_in[4];
    const float* be1= (const float*)d_in[5];
    const float* W2 = (const float*)d_in[6];
    const float* b2 = (const float*)d_in[7];
    const float* W3 = (const float*)d_in[8];
    const float* b3 = (const float*)d_in[9];
    const float* g3 = (const float*)d_in[10];
    const float* be3= (const float*)d_in[11];
    const float* W4 = (const float*)d_in[12];
    const float* b4 = (const float*)d_in[13];
    const float* g4 = (const float*)d_in[14];
    const float* be4= (const float*)d_in[15];

    int nrows = in_sizes[0] / 128;

    const int att_smem = ATT_SMEM_WORDS * 4;   // 108,320 B -> 2 CTAs/SM
    const int fin_smem = FIN_SMEM_WORDS * 4;   //  89,984 B -> 2 CTAs/SM
    cudaFuncSetAttribute(att_kernel,   cudaFuncAttributeMaxDynamicSharedMemorySize, att_smem);
    cudaFuncSetAttribute(final_kernel, cudaFuncAttributeMaxDynamicSharedMemorySize, fin_smem);

    detect_kernel<<<1, 256>>>(batch, nrows);
    bounds_kernel<<<NGRAPH / 256, 256>>>(batch, nrows);
    prep_kernel<<<304, 256>>>(W1, W3, W4);
    att_kernel<<<nrows / 128, 256, att_smem>>>(feat, b1, g1, be1, W2, b2);
    aggregate_kernel<<<NGRAPH, 256>>>(feat);
    final_kernel<<<NGRAPH / 16, 256, fin_smem>>>(b3, g3, be3, b4, g4, be4, (float*)d_out);
}